// round 1
// baseline (speedup 1.0000x reference)
#include <cuda_runtime.h>

// ---------------------------------------------------------------------------
// Problem constants
// ---------------------------------------------------------------------------
#define S_LEN  2048
#define NHEAD  16
#define HDIM   64
#define BATCH  2
#define EMB    1024
#define MROWS  (BATCH * S_LEN)   // 4096

// ---------------------------------------------------------------------------
// Scratch (allocation-free rule: __device__ globals)
// ---------------------------------------------------------------------------
__device__ __align__(16) float g_q[(size_t)MROWS * EMB];
__device__ __align__(16) float g_k[(size_t)MROWS * EMB];
__device__ __align__(16) float g_v[(size_t)MROWS * EMB];
__device__ __align__(16) float g_attn[(size_t)MROWS * EMB];

// ---------------------------------------------------------------------------
// Tiled SGEMM: C = A(MxK) * W^T(NxK) + bias, fp32.
// LAYOUT 0: C[m*N + n]   (plain row-major)
// LAYOUT 1: head-split:  C[((b*NHEAD + h)*S_LEN + s)*HDIM + d]
//           with m = b*S_LEN + s, n = h*HDIM + d
// BM=BN=128, BK=16, 256 threads, 8x8 per-thread microtile.
// ---------------------------------------------------------------------------
#define BM 128
#define BN 128
#define BK 16

template <int LAYOUT>
__global__ __launch_bounds__(256)
void gemm_bias(const float* __restrict__ A,
               const float* __restrict__ W,
               const float* __restrict__ bias,
               float* __restrict__ C,
               int M, int N, int K)
{
    __shared__ __align__(16) float As[BK][BM];
    __shared__ __align__(16) float Ws[BK][BN];

    const int tid = threadIdx.x;
    const int tx = tid & 15;     // 0..15 -> N direction
    const int ty = tid >> 4;     // 0..15 -> M direction
    const int bm = blockIdx.y * BM;
    const int bn = blockIdx.x * BN;

    const float* Ap = A + (size_t)bm * K;
    const float* Wp = W + (size_t)bn * K;

    float acc[8][8];
#pragma unroll
    for (int i = 0; i < 8; i++)
#pragma unroll
        for (int j = 0; j < 8; j++) acc[i][j] = 0.f;

    for (int k0 = 0; k0 < K; k0 += BK) {
        // Cooperative load: 128 rows x 16 k, transposed into smem.
#pragma unroll
        for (int i = 0; i < 2; i++) {
            int id  = tid + i * 256;       // 0..511 float4 slots
            int row = id >> 2;             // 0..127
            int c4  = (id & 3) << 2;       // 0,4,8,12
            float4 va = *reinterpret_cast<const float4*>(Ap + (size_t)row * K + k0 + c4);
            As[c4 + 0][row] = va.x;
            As[c4 + 1][row] = va.y;
            As[c4 + 2][row] = va.z;
            As[c4 + 3][row] = va.w;
            float4 vw = *reinterpret_cast<const float4*>(Wp + (size_t)row * K + k0 + c4);
            Ws[c4 + 0][row] = vw.x;
            Ws[c4 + 1][row] = vw.y;
            Ws[c4 + 2][row] = vw.z;
            Ws[c4 + 3][row] = vw.w;
        }
        __syncthreads();

#pragma unroll
        for (int k = 0; k < BK; k++) {
            float a[8], b[8];
            *reinterpret_cast<float4*>(a)     = *reinterpret_cast<const float4*>(&As[k][ty * 8]);
            *reinterpret_cast<float4*>(a + 4) = *reinterpret_cast<const float4*>(&As[k][ty * 8 + 4]);
            *reinterpret_cast<float4*>(b)     = *reinterpret_cast<const float4*>(&Ws[k][tx * 8]);
            *reinterpret_cast<float4*>(b + 4) = *reinterpret_cast<const float4*>(&Ws[k][tx * 8 + 4]);
#pragma unroll
            for (int i = 0; i < 8; i++)
#pragma unroll
                for (int j = 0; j < 8; j++)
                    acc[i][j] += a[i] * b[j];
        }
        __syncthreads();
    }

    // Epilogue: bias + layout remap
#pragma unroll
    for (int i = 0; i < 8; i++) {
        int r = bm + ty * 8 + i;
#pragma unroll
        for (int j = 0; j < 8; j++) {
            int c = bn + tx * 8 + j;
            float v = acc[i][j] + bias[c];
            if (LAYOUT == 0) {
                C[(size_t)r * N + c] = v;
            } else {
                int b = r >> 11;            // r / 2048
                int s = r & 2047;
                int h = c >> 6;             // c / 64
                int d = c & 63;
                C[(((size_t)(b * NHEAD + h) << 11) + s) * HDIM + d] = v;
            }
        }
    }
}

// ---------------------------------------------------------------------------
// Causal flash attention, fp32.
// Q/K/V in (B*H, S, D) layout. Output written in (B, S, H*D) plain layout
// so the final GEMM reads it as a 4096x1024 row-major matrix.
// Block: one (b,h), one 64-row query tile. 256 threads = 16x16 grid,
// each thread owns a 4x4 tile of scores / output.
// smem: Qs (Q transposed) + KP (K transposed, reused for P) + Vs = 48 KB.
// ---------------------------------------------------------------------------
__global__ __launch_bounds__(256)
void attn_kernel(const float* __restrict__ Q,
                 const float* __restrict__ K,
                 const float* __restrict__ V,
                 float* __restrict__ O)
{
    __shared__ __align__(16) float Qs[HDIM][64];   // [d][r]
    __shared__ __align__(16) float KP[64][64];     // [d][j] for K, then [r][j] for P
    __shared__ __align__(16) float Vs[64][HDIM];   // [j][d]

    const int tid = threadIdx.x;
    const int tx  = tid & 15;
    const int ty  = tid >> 4;
    const int bh  = blockIdx.y;                       // b*NHEAD + h
    const int qt  = (int)gridDim.x - 1 - (int)blockIdx.x;  // heavy tiles first
    const int q0  = qt << 6;

    const float* qp = Q + (size_t)bh * S_LEN * HDIM;
    const float* kp = K + (size_t)bh * S_LEN * HDIM;
    const float* vp = V + (size_t)bh * S_LEN * HDIM;

    // Load Q tile transposed: Qs[d][r] = Q[q0+r][d]
#pragma unroll
    for (int i = 0; i < 4; i++) {
        int id = tid + i * 256;        // 0..1023 float4 slots
        int r  = id >> 4;              // 0..63
        int c4 = (id & 15) << 2;       // 0..60
        float4 vq = *reinterpret_cast<const float4*>(qp + (size_t)(q0 + r) * HDIM + c4);
        Qs[c4 + 0][r] = vq.x;
        Qs[c4 + 1][r] = vq.y;
        Qs[c4 + 2][r] = vq.z;
        Qs[c4 + 3][r] = vq.w;
    }

    float m_i[4], l_i[4], acc[4][4];
#pragma unroll
    for (int i = 0; i < 4; i++) {
        m_i[i] = -1e30f;
        l_i[i] = 0.f;
#pragma unroll
        for (int j = 0; j < 4; j++) acc[i][j] = 0.f;
    }

    const float sm_scale = 0.125f;  // 1/sqrt(64)

    for (int kt = 0; kt <= qt; kt++) {
        int k0 = kt << 6;
        __syncthreads();   // protect smem reuse across iterations

        // Load K transposed + V natural
#pragma unroll
        for (int i = 0; i < 4; i++) {
            int id = tid + i * 256;
            int r  = id >> 4;
            int c4 = (id & 15) << 2;
            float4 vk = *reinterpret_cast<const float4*>(kp + (size_t)(k0 + r) * HDIM + c4);
            KP[c4 + 0][r] = vk.x;
            KP[c4 + 1][r] = vk.y;
            KP[c4 + 2][r] = vk.z;
            KP[c4 + 3][r] = vk.w;
            *reinterpret_cast<float4*>(&Vs[r][c4]) =
                *reinterpret_cast<const float4*>(vp + (size_t)(k0 + r) * HDIM + c4);
        }
        __syncthreads();

        // Scores: S = Q * K^T  (4x4 per thread)
        float s[4][4];
#pragma unroll
        for (int i = 0; i < 4; i++)
#pragma unroll
            for (int j = 0; j < 4; j++) s[i][j] = 0.f;

#pragma unroll
        for (int d = 0; d < HDIM; d++) {
            float a[4], b[4];
            *reinterpret_cast<float4*>(a) = *reinterpret_cast<const float4*>(&Qs[d][ty * 4]);
            *reinterpret_cast<float4*>(b) = *reinterpret_cast<const float4*>(&KP[d][tx * 4]);
#pragma unroll
            for (int i = 0; i < 4; i++)
#pragma unroll
                for (int j = 0; j < 4; j++)
                    s[i][j] += a[i] * b[j];
        }

        // Scale + causal mask (diagonal tile only)
#pragma unroll
        for (int i = 0; i < 4; i++)
#pragma unroll
            for (int j = 0; j < 4; j++) {
                s[i][j] *= sm_scale;
                if (kt == qt && (tx * 4 + j) > (ty * 4 + i)) s[i][j] = -1e30f;
            }

        // Online softmax (row reductions over 16 tx-lanes via shfl)
        float p[4][4];
#pragma unroll
        for (int i = 0; i < 4; i++) {
            float rm = s[i][0];
#pragma unroll
            for (int j = 1; j < 4; j++) rm = fmaxf(rm, s[i][j]);
#pragma unroll
            for (int off = 1; off < 16; off <<= 1)
                rm = fmaxf(rm, __shfl_xor_sync(0xffffffffu, rm, off));

            float m_new = fmaxf(m_i[i], rm);
            float rescale = expf(m_i[i] - m_new);
            m_i[i] = m_new;

            float rs = 0.f;
#pragma unroll
            for (int j = 0; j < 4; j++) {
                p[i][j] = expf(s[i][j] - m_new);
                rs += p[i][j];
            }
#pragma unroll
            for (int off = 1; off < 16; off <<= 1)
                rs += __shfl_xor_sync(0xffffffffu, rs, off);

            l_i[i] = l_i[i] * rescale + rs;
#pragma unroll
            for (int j = 0; j < 4; j++) acc[i][j] *= rescale;
        }

        __syncthreads();   // everyone done reading KP (K data)

        // Write P into KP (natural layout [r][j]) as float4
#pragma unroll
        for (int i = 0; i < 4; i++)
            *reinterpret_cast<float4*>(&KP[ty * 4 + i][tx * 4]) =
                *reinterpret_cast<const float4*>(&p[i][0]);
        __syncthreads();

        // O += P * V
#pragma unroll
        for (int j4 = 0; j4 < 16; j4++) {
            float pa[4][4], vb[4][4];
#pragma unroll
            for (int i = 0; i < 4; i++)
                *reinterpret_cast<float4*>(pa[i]) =
                    *reinterpret_cast<const float4*>(&KP[ty * 4 + i][j4 * 4]);
#pragma unroll
            for (int t = 0; t < 4; t++)
                *reinterpret_cast<float4*>(vb[t]) =
                    *reinterpret_cast<const float4*>(&Vs[j4 * 4 + t][tx * 4]);
#pragma unroll
            for (int i = 0; i < 4; i++)
#pragma unroll
                for (int t = 0; t < 4; t++)
#pragma unroll
                    for (int j = 0; j < 4; j++)
                        acc[i][j] += pa[i][t] * vb[t][j];
        }
    }

    // Finalize: divide by l, write (B, S, H*D) layout
    const int b = bh >> 4;
    const int h = bh & 15;
#pragma unroll
    for (int i = 0; i < 4; i++) {
        float inv = 1.f / l_i[i];
        int sr = q0 + ty * 4 + i;
#pragma unroll
        for (int j = 0; j < 4; j++) {
            O[((size_t)(b * S_LEN + sr)) * EMB + h * HDIM + tx * 4 + j] = acc[i][j] * inv;
        }
    }
}

// ---------------------------------------------------------------------------
// Launcher
// ---------------------------------------------------------------------------
extern "C" void kernel_launch(void* const* d_in, const int* in_sizes, int n_in,
                              void* d_out, int out_size)
{
    const float* x  = (const float*)d_in[0];
    const float* Wq = (const float*)d_in[1];
    const float* bq = (const float*)d_in[2];
    const float* Wk = (const float*)d_in[3];
    const float* bk = (const float*)d_in[4];
    const float* Wv = (const float*)d_in[5];
    const float* bv = (const float*)d_in[6];
    const float* Wo = (const float*)d_in[7];
    const float* bo = (const float*)d_in[8];
    float* out = (float*)d_out;

    float *q, *k, *v, *attn;
    cudaGetSymbolAddress((void**)&q,    g_q);
    cudaGetSymbolAddress((void**)&k,    g_k);
    cudaGetSymbolAddress((void**)&v,    g_v);
    cudaGetSymbolAddress((void**)&attn, g_attn);

    dim3 gg(EMB / BN, MROWS / BM);   // (8, 32)
    gemm_bias<1><<<gg, 256>>>(x, Wq, bq, q, MROWS, EMB, EMB);
    gemm_bias<1><<<gg, 256>>>(x, Wk, bk, k, MROWS, EMB, EMB);
    gemm_bias<1><<<gg, 256>>>(x, Wv, bv, v, MROWS, EMB, EMB);

    dim3 ga(S_LEN / 64, BATCH * NHEAD);   // (32, 32)
    attn_kernel<<<ga, 256>>>(q, k, v, attn);

    gemm_bias<0><<<gg, 256>>>(attn, Wo, bo, out, MROWS, EMB, EMB);
}

// round 3
// speedup vs baseline: 1.4704x; 1.4704x over previous
#include <cuda_runtime.h>
#include <cstdint>

// ---------------------------------------------------------------------------
// Problem constants
// ---------------------------------------------------------------------------
#define S_LEN  2048
#define NHEAD  16
#define HDIM   64
#define BATCH  2
#define EMB    1024
#define MROWS  (BATCH * S_LEN)   // 4096

// ---------------------------------------------------------------------------
// Scratch (allocation-free rule: __device__ globals)
// ---------------------------------------------------------------------------
__device__ __align__(16) float g_q[(size_t)MROWS * EMB];
__device__ __align__(16) float g_k[(size_t)MROWS * EMB];
__device__ __align__(16) float g_v[(size_t)MROWS * EMB];
__device__ __align__(16) float g_attn[(size_t)MROWS * EMB];

// ---------------------------------------------------------------------------
// tf32 helpers (base ISA, sm_80+: works on plain sm_103 target)
// ---------------------------------------------------------------------------
__device__ __forceinline__ uint32_t tf32r(float x) {   // round-to-nearest tf32
    uint32_t o;
    asm("cvt.rna.tf32.f32 %0, %1;" : "=r"(o) : "f"(x));
    return o;
}

#define MMA_TF32(d, a, b)                                                   \
    asm volatile("mma.sync.aligned.m16n8k8.row.col.f32.tf32.tf32.f32 "      \
        "{%0,%1,%2,%3}, {%4,%5,%6,%7}, {%8,%9}, {%0,%1,%2,%3};"             \
        : "+f"((d)[0]), "+f"((d)[1]), "+f"((d)[2]), "+f"((d)[3])            \
        : "r"((a)[0]), "r"((a)[1]), "r"((a)[2]), "r"((a)[3]),               \
          "r"((b)[0]), "r"((b)[1]))

// ---------------------------------------------------------------------------
// tf32 mma.sync GEMM:  C(MxN) = A(MxK) @ W^T(NxK) + bias
// CTA 128x128, 8 warps (2M x 4N), warp tile 64x32, BK=16, double-buffered.
// smem layout [k][m] (A) and [k][n] (B), stride 132 floats (conflict pad).
// LAYOUT 0: plain row-major.  LAYOUT 1: head-split (B,H,S,D).
// ---------------------------------------------------------------------------
#define BKC 16

template <int LAYOUT>
__global__ __launch_bounds__(256)
void gemm_mma(const float* __restrict__ A,
              const float* __restrict__ W,
              const float* __restrict__ bias,
              float* __restrict__ C)
{
    __shared__ float As[2][BKC][132];
    __shared__ float Bs[2][BKC][132];

    const int tid  = threadIdx.x;
    const int lane = tid & 31;
    const int wid  = tid >> 5;
    const int gID  = lane >> 2;   // 0..7
    const int tig  = lane & 3;    // 0..3
    const int wm   = wid >> 2;    // 0..1  (M direction, 64 rows each)
    const int wn   = wid & 3;     // 0..3  (N direction, 32 cols each)
    const int bm   = blockIdx.y * 128;
    const int bn   = blockIdx.x * 128;

    const float* Ap = A + (size_t)bm * EMB;
    const float* Wp = W + (size_t)bn * EMB;

    float acc[4][4][4];
#pragma unroll
    for (int mf = 0; mf < 4; mf++)
#pragma unroll
        for (int nf = 0; nf < 4; nf++)
#pragma unroll
            for (int r = 0; r < 4; r++) acc[mf][nf][r] = 0.f;

    // Per-thread global-load coordinates: 512 float4 slots per matrix per chunk
    // (128 rows x 16 k), 2 slots per thread.
    const int slot0_row = (tid + 0)   >> 2;          // 0..63
    const int slot1_row = (tid + 256) >> 2;          // 64..127
    const int slot0_c4  = (tid & 3) << 2;            // 0,4,8,12
    const int slot1_c4  = slot0_c4;

    // prologue: chunk 0 -> buf 0
    {
        float4 a0 = *reinterpret_cast<const float4*>(Ap + (size_t)slot0_row * EMB + slot0_c4);
        float4 a1 = *reinterpret_cast<const float4*>(Ap + (size_t)slot1_row * EMB + slot1_c4);
        float4 b0 = *reinterpret_cast<const float4*>(Wp + (size_t)slot0_row * EMB + slot0_c4);
        float4 b1 = *reinterpret_cast<const float4*>(Wp + (size_t)slot1_row * EMB + slot1_c4);
        As[0][slot0_c4 + 0][slot0_row] = __uint_as_float(tf32r(a0.x));
        As[0][slot0_c4 + 1][slot0_row] = __uint_as_float(tf32r(a0.y));
        As[0][slot0_c4 + 2][slot0_row] = __uint_as_float(tf32r(a0.z));
        As[0][slot0_c4 + 3][slot0_row] = __uint_as_float(tf32r(a0.w));
        As[0][slot1_c4 + 0][slot1_row] = __uint_as_float(tf32r(a1.x));
        As[0][slot1_c4 + 1][slot1_row] = __uint_as_float(tf32r(a1.y));
        As[0][slot1_c4 + 2][slot1_row] = __uint_as_float(tf32r(a1.z));
        As[0][slot1_c4 + 3][slot1_row] = __uint_as_float(tf32r(a1.w));
        Bs[0][slot0_c4 + 0][slot0_row] = __uint_as_float(tf32r(b0.x));
        Bs[0][slot0_c4 + 1][slot0_row] = __uint_as_float(tf32r(b0.y));
        Bs[0][slot0_c4 + 2][slot0_row] = __uint_as_float(tf32r(b0.z));
        Bs[0][slot0_c4 + 3][slot0_row] = __uint_as_float(tf32r(b0.w));
        Bs[0][slot1_c4 + 0][slot1_row] = __uint_as_float(tf32r(b1.x));
        Bs[0][slot1_c4 + 1][slot1_row] = __uint_as_float(tf32r(b1.y));
        Bs[0][slot1_c4 + 2][slot1_row] = __uint_as_float(tf32r(b1.z));
        Bs[0][slot1_c4 + 3][slot1_row] = __uint_as_float(tf32r(b1.w));
    }
    __syncthreads();

    const int NCH = EMB / BKC;   // 64

#pragma unroll 1
    for (int c = 0; c < NCH; c++) {
        const int buf = c & 1;

        // Stage next chunk's globals into registers (LDG overlaps MMA below)
        float4 a0, a1, b0, b1;
        const bool more = (c + 1 < NCH);
        if (more) {
            const int k0 = (c + 1) * BKC;
            a0 = *reinterpret_cast<const float4*>(Ap + (size_t)slot0_row * EMB + k0 + slot0_c4);
            a1 = *reinterpret_cast<const float4*>(Ap + (size_t)slot1_row * EMB + k0 + slot1_c4);
            b0 = *reinterpret_cast<const float4*>(Wp + (size_t)slot0_row * EMB + k0 + slot0_c4);
            b1 = *reinterpret_cast<const float4*>(Wp + (size_t)slot1_row * EMB + k0 + slot1_c4);
        }

        // Compute on buf
#pragma unroll
        for (int ks = 0; ks < 2; ks++) {
            const int kk = ks * 8;
            uint32_t afr[4][4], bfr[4][2];
#pragma unroll
            for (int mf = 0; mf < 4; mf++) {
                const int m0 = wm * 64 + mf * 16 + gID;
                afr[mf][0] = __float_as_uint(As[buf][kk + tig][m0]);
                afr[mf][1] = __float_as_uint(As[buf][kk + tig][m0 + 8]);
                afr[mf][2] = __float_as_uint(As[buf][kk + tig + 4][m0]);
                afr[mf][3] = __float_as_uint(As[buf][kk + tig + 4][m0 + 8]);
            }
#pragma unroll
            for (int nf = 0; nf < 4; nf++) {
                const int n0 = wn * 32 + nf * 8 + gID;
                bfr[nf][0] = __float_as_uint(Bs[buf][kk + tig][n0]);
                bfr[nf][1] = __float_as_uint(Bs[buf][kk + tig + 4][n0]);
            }
#pragma unroll
            for (int mf = 0; mf < 4; mf++)
#pragma unroll
                for (int nf = 0; nf < 4; nf++)
                    MMA_TF32(acc[mf][nf], afr[mf], bfr[nf]);
        }

        // Store staged chunk into the other buffer
        if (more) {
            const int ob = buf ^ 1;
            As[ob][slot0_c4 + 0][slot0_row] = __uint_as_float(tf32r(a0.x));
            As[ob][slot0_c4 + 1][slot0_row] = __uint_as_float(tf32r(a0.y));
            As[ob][slot0_c4 + 2][slot0_row] = __uint_as_float(tf32r(a0.z));
            As[ob][slot0_c4 + 3][slot0_row] = __uint_as_float(tf32r(a0.w));
            As[ob][slot1_c4 + 0][slot1_row] = __uint_as_float(tf32r(a1.x));
            As[ob][slot1_c4 + 1][slot1_row] = __uint_as_float(tf32r(a1.y));
            As[ob][slot1_c4 + 2][slot1_row] = __uint_as_float(tf32r(a1.z));
            As[ob][slot1_c4 + 3][slot1_row] = __uint_as_float(tf32r(a1.w));
            Bs[ob][slot0_c4 + 0][slot0_row] = __uint_as_float(tf32r(b0.x));
            Bs[ob][slot0_c4 + 1][slot0_row] = __uint_as_float(tf32r(b0.y));
            Bs[ob][slot0_c4 + 2][slot0_row] = __uint_as_float(tf32r(b0.z));
            Bs[ob][slot0_c4 + 3][slot0_row] = __uint_as_float(tf32r(b0.w));
            Bs[ob][slot1_c4 + 0][slot1_row] = __uint_as_float(tf32r(b1.x));
            Bs[ob][slot1_c4 + 1][slot1_row] = __uint_as_float(tf32r(b1.y));
            Bs[ob][slot1_c4 + 2][slot1_row] = __uint_as_float(tf32r(b1.z));
            Bs[ob][slot1_c4 + 3][slot1_row] = __uint_as_float(tf32r(b1.w));
        }
        __syncthreads();
    }

    // Epilogue: bias + layout remap, float2 stores
#pragma unroll
    for (int mf = 0; mf < 4; mf++) {
#pragma unroll
        for (int nf = 0; nf < 4; nf++) {
            const int r0 = bm + wm * 64 + mf * 16 + gID;
            const int r1 = r0 + 8;
            const int cc = bn + wn * 32 + nf * 8 + tig * 2;
            const float bi0 = bias[cc];
            const float bi1 = bias[cc + 1];
            float2 v0 = make_float2(acc[mf][nf][0] + bi0, acc[mf][nf][1] + bi1);
            float2 v1 = make_float2(acc[mf][nf][2] + bi0, acc[mf][nf][3] + bi1);
            if (LAYOUT == 0) {
                *reinterpret_cast<float2*>(C + (size_t)r0 * EMB + cc) = v0;
                *reinterpret_cast<float2*>(C + (size_t)r1 * EMB + cc) = v1;
            } else {
                const int hh = cc >> 6;
                const int dd = cc & 63;
                {
                    const int bb = r0 >> 11, ss = r0 & 2047;
                    *reinterpret_cast<float2*>(
                        C + (((size_t)(bb * NHEAD + hh) << 11) + ss) * HDIM + dd) = v0;
                }
                {
                    const int bb = r1 >> 11, ss = r1 & 2047;
                    *reinterpret_cast<float2*>(
                        C + (((size_t)(bb * NHEAD + hh) << 11) + ss) * HDIM + dd) = v1;
                }
            }
        }
    }
}

// ---------------------------------------------------------------------------
// Causal flash attention, fp32 (unchanged — known good).
// ---------------------------------------------------------------------------
__global__ __launch_bounds__(256)
void attn_kernel(const float* __restrict__ Q,
                 const float* __restrict__ K,
                 const float* __restrict__ V,
                 float* __restrict__ O)
{
    __shared__ __align__(16) float Qs[HDIM][64];
    __shared__ __align__(16) float KP[64][64];
    __shared__ __align__(16) float Vs[64][HDIM];

    const int tid = threadIdx.x;
    const int tx  = tid & 15;
    const int ty  = tid >> 4;
    const int bh  = blockIdx.y;
    const int qt  = (int)gridDim.x - 1 - (int)blockIdx.x;
    const int q0  = qt << 6;

    const float* qp = Q + (size_t)bh * S_LEN * HDIM;
    const float* kp = K + (size_t)bh * S_LEN * HDIM;
    const float* vp = V + (size_t)bh * S_LEN * HDIM;

#pragma unroll
    for (int i = 0; i < 4; i++) {
        int id = tid + i * 256;
        int r  = id >> 4;
        int c4 = (id & 15) << 2;
        float4 vq = *reinterpret_cast<const float4*>(qp + (size_t)(q0 + r) * HDIM + c4);
        Qs[c4 + 0][r] = vq.x;
        Qs[c4 + 1][r] = vq.y;
        Qs[c4 + 2][r] = vq.z;
        Qs[c4 + 3][r] = vq.w;
    }

    float m_i[4], l_i[4], acc[4][4];
#pragma unroll
    for (int i = 0; i < 4; i++) {
        m_i[i] = -1e30f;
        l_i[i] = 0.f;
#pragma unroll
        for (int j = 0; j < 4; j++) acc[i][j] = 0.f;
    }

    const float sm_scale = 0.125f;

    for (int kt = 0; kt <= qt; kt++) {
        int k0 = kt << 6;
        __syncthreads();
#pragma unroll
        for (int i = 0; i < 4; i++) {
            int id = tid + i * 256;
            int r  = id >> 4;
            int c4 = (id & 15) << 2;
            float4 vk = *reinterpret_cast<const float4*>(kp + (size_t)(k0 + r) * HDIM + c4);
            KP[c4 + 0][r] = vk.x;
            KP[c4 + 1][r] = vk.y;
            KP[c4 + 2][r] = vk.z;
            KP[c4 + 3][r] = vk.w;
            *reinterpret_cast<float4*>(&Vs[r][c4]) =
                *reinterpret_cast<const float4*>(vp + (size_t)(k0 + r) * HDIM + c4);
        }
        __syncthreads();

        float s[4][4];
#pragma unroll
        for (int i = 0; i < 4; i++)
#pragma unroll
            for (int j = 0; j < 4; j++) s[i][j] = 0.f;

#pragma unroll
        for (int d = 0; d < HDIM; d++) {
            float a[4], b[4];
            *reinterpret_cast<float4*>(a) = *reinterpret_cast<const float4*>(&Qs[d][ty * 4]);
            *reinterpret_cast<float4*>(b) = *reinterpret_cast<const float4*>(&KP[d][tx * 4]);
#pragma unroll
            for (int i = 0; i < 4; i++)
#pragma unroll
                for (int j = 0; j < 4; j++)
                    s[i][j] += a[i] * b[j];
        }

#pragma unroll
        for (int i = 0; i < 4; i++)
#pragma unroll
            for (int j = 0; j < 4; j++) {
                s[i][j] *= sm_scale;
                if (kt == qt && (tx * 4 + j) > (ty * 4 + i)) s[i][j] = -1e30f;
            }

        float p[4][4];
#pragma unroll
        for (int i = 0; i < 4; i++) {
            float rm = s[i][0];
#pragma unroll
            for (int j = 1; j < 4; j++) rm = fmaxf(rm, s[i][j]);
#pragma unroll
            for (int off = 1; off < 16; off <<= 1)
                rm = fmaxf(rm, __shfl_xor_sync(0xffffffffu, rm, off));

            float m_new = fmaxf(m_i[i], rm);
            float rescale = expf(m_i[i] - m_new);
            m_i[i] = m_new;

            float rs = 0.f;
#pragma unroll
            for (int j = 0; j < 4; j++) {
                p[i][j] = expf(s[i][j] - m_new);
                rs += p[i][j];
            }
#pragma unroll
            for (int off = 1; off < 16; off <<= 1)
                rs += __shfl_xor_sync(0xffffffffu, rs, off);

            l_i[i] = l_i[i] * rescale + rs;
#pragma unroll
            for (int j = 0; j < 4; j++) acc[i][j] *= rescale;
        }

        __syncthreads();
#pragma unroll
        for (int i = 0; i < 4; i++)
            *reinterpret_cast<float4*>(&KP[ty * 4 + i][tx * 4]) =
                *reinterpret_cast<const float4*>(&p[i][0]);
        __syncthreads();

#pragma unroll
        for (int j4 = 0; j4 < 16; j4++) {
            float pa[4][4], vb[4][4];
#pragma unroll
            for (int i = 0; i < 4; i++)
                *reinterpret_cast<float4*>(pa[i]) =
                    *reinterpret_cast<const float4*>(&KP[ty * 4 + i][j4 * 4]);
#pragma unroll
            for (int t = 0; t < 4; t++)
                *reinterpret_cast<float4*>(vb[t]) =
                    *reinterpret_cast<const float4*>(&Vs[j4 * 4 + t][tx * 4]);
#pragma unroll
            for (int i = 0; i < 4; i++)
#pragma unroll
                for (int t = 0; t < 4; t++)
#pragma unroll
                    for (int j = 0; j < 4; j++)
                        acc[i][j] += pa[i][t] * vb[t][j];
        }
    }

    const int b = bh >> 4;
    const int h = bh & 15;
#pragma unroll
    for (int i = 0; i < 4; i++) {
        float inv = 1.f / l_i[i];
        int sr = q0 + ty * 4 + i;
#pragma unroll
        for (int j = 0; j < 4; j++) {
            O[((size_t)(b * S_LEN + sr)) * EMB + h * HDIM + tx * 4 + j] = acc[i][j] * inv;
        }
    }
}

// ---------------------------------------------------------------------------
// Launcher
// ---------------------------------------------------------------------------
extern "C" void kernel_launch(void* const* d_in, const int* in_sizes, int n_in,
                              void* d_out, int out_size)
{
    const float* x  = (const float*)d_in[0];
    const float* Wq = (const float*)d_in[1];
    const float* bq = (const float*)d_in[2];
    const float* Wk = (const float*)d_in[3];
    const float* bk = (const float*)d_in[4];
    const float* Wv = (const float*)d_in[5];
    const float* bv = (const float*)d_in[6];
    const float* Wo = (const float*)d_in[7];
    const float* bo = (const float*)d_in[8];
    float* out = (float*)d_out;

    float *q, *k, *v, *attn;
    cudaGetSymbolAddress((void**)&q,    g_q);
    cudaGetSymbolAddress((void**)&k,    g_k);
    cudaGetSymbolAddress((void**)&v,    g_v);
    cudaGetSymbolAddress((void**)&attn, g_attn);

    dim3 gg(EMB / 128, MROWS / 128);   // (8, 32)
    gemm_mma<1><<<gg, 256>>>(x, Wq, bq, q);
    gemm_mma<1><<<gg, 256>>>(x, Wk, bk, k);
    gemm_mma<1><<<gg, 256>>>(x, Wv, bv, v);

    dim3 ga(S_LEN / 64, BATCH * NHEAD);   // (32, 32)
    attn_kernel<<<ga, 256>>>(q, k, v, attn);

    gemm_mma<0><<<gg, 256>>>(attn, Wo, bo, out);
}

// round 4
// speedup vs baseline: 2.7358x; 1.8605x over previous
#include <cuda_runtime.h>
#include <cstdint>

// ---------------------------------------------------------------------------
// Problem constants
// ---------------------------------------------------------------------------
#define S_LEN  2048
#define NHEAD  16
#define HDIM   64
#define BATCH  2
#define EMB    1024
#define MROWS  (BATCH * S_LEN)   // 4096

// ---------------------------------------------------------------------------
// Scratch (allocation-free rule: __device__ globals)
// ---------------------------------------------------------------------------
__device__ __align__(16) float g_q[(size_t)MROWS * EMB];
__device__ __align__(16) float g_k[(size_t)MROWS * EMB];
__device__ __align__(16) float g_v[(size_t)MROWS * EMB];
__device__ __align__(16) float g_attn[(size_t)MROWS * EMB];

// ---------------------------------------------------------------------------
// tf32 helpers (base ISA, sm_80+)
// ---------------------------------------------------------------------------
__device__ __forceinline__ uint32_t tf32r(float x) {   // round-to-nearest tf32
    uint32_t o;
    asm("cvt.rna.tf32.f32 %0, %1;" : "=r"(o) : "f"(x));
    return o;
}
__device__ __forceinline__ float tf32rf(float x) { return __uint_as_float(tf32r(x)); }

#define MMA_TF32(d, a, b)                                                   \
    asm volatile("mma.sync.aligned.m16n8k8.row.col.f32.tf32.tf32.f32 "      \
        "{%0,%1,%2,%3}, {%4,%5,%6,%7}, {%8,%9}, {%0,%1,%2,%3};"             \
        : "+f"((d)[0]), "+f"((d)[1]), "+f"((d)[2]), "+f"((d)[3])            \
        : "r"((a)[0]), "r"((a)[1]), "r"((a)[2]), "r"((a)[3]),               \
          "r"((b)[0]), "r"((b)[1]))

// exp2 on the FMA pipe: no MUFU, no CVT. x must be <= 0.
__device__ __forceinline__ float exp2_poly(float x) {
    x = fmaxf(x, -126.f);
    float y = x + 12582912.f;              // 1.5 * 2^23  (round-to-nearest int)
    int   iy = __float_as_int(y);
    float n  = y - 12582912.f;
    float f  = x - n;                      // f in [-0.5, 0.5]
    float p  = 0.0013333558f;
    p = fmaf(p, f, 0.0096181291f);
    p = fmaf(p, f, 0.0555041086f);
    p = fmaf(p, f, 0.2402265069f);
    p = fmaf(p, f, 0.6931471806f);
    p = fmaf(p, f, 1.0f);
    return __int_as_float((iy + 127) << 23) * p;   // 2^n * poly(f)
}

// ---------------------------------------------------------------------------
// tf32 mma.sync GEMM (unchanged from R3 — proven):
// C(MxN) = A(MxK) @ W^T(NxK) + bias.  CTA 128x128, 8 warps, BK=16, dbl-buf.
// ---------------------------------------------------------------------------
#define BKC 16

template <int LAYOUT>
__global__ __launch_bounds__(256)
void gemm_mma(const float* __restrict__ A,
              const float* __restrict__ W,
              const float* __restrict__ bias,
              float* __restrict__ C)
{
    __shared__ float As[2][BKC][132];
    __shared__ float Bs[2][BKC][132];

    const int tid  = threadIdx.x;
    const int lane = tid & 31;
    const int wid  = tid >> 5;
    const int gID  = lane >> 2;
    const int tig  = lane & 3;
    const int wm   = wid >> 2;
    const int wn   = wid & 3;
    const int bm   = blockIdx.y * 128;
    const int bn   = blockIdx.x * 128;

    const float* Ap = A + (size_t)bm * EMB;
    const float* Wp = W + (size_t)bn * EMB;

    float acc[4][4][4];
#pragma unroll
    for (int mf = 0; mf < 4; mf++)
#pragma unroll
        for (int nf = 0; nf < 4; nf++)
#pragma unroll
            for (int r = 0; r < 4; r++) acc[mf][nf][r] = 0.f;

    const int slot0_row = (tid + 0)   >> 2;
    const int slot1_row = (tid + 256) >> 2;
    const int slot0_c4  = (tid & 3) << 2;
    const int slot1_c4  = slot0_c4;

    {
        float4 a0 = *reinterpret_cast<const float4*>(Ap + (size_t)slot0_row * EMB + slot0_c4);
        float4 a1 = *reinterpret_cast<const float4*>(Ap + (size_t)slot1_row * EMB + slot1_c4);
        float4 b0 = *reinterpret_cast<const float4*>(Wp + (size_t)slot0_row * EMB + slot0_c4);
        float4 b1 = *reinterpret_cast<const float4*>(Wp + (size_t)slot1_row * EMB + slot1_c4);
        As[0][slot0_c4 + 0][slot0_row] = tf32rf(a0.x);
        As[0][slot0_c4 + 1][slot0_row] = tf32rf(a0.y);
        As[0][slot0_c4 + 2][slot0_row] = tf32rf(a0.z);
        As[0][slot0_c4 + 3][slot0_row] = tf32rf(a0.w);
        As[0][slot1_c4 + 0][slot1_row] = tf32rf(a1.x);
        As[0][slot1_c4 + 1][slot1_row] = tf32rf(a1.y);
        As[0][slot1_c4 + 2][slot1_row] = tf32rf(a1.z);
        As[0][slot1_c4 + 3][slot1_row] = tf32rf(a1.w);
        Bs[0][slot0_c4 + 0][slot0_row] = tf32rf(b0.x);
        Bs[0][slot0_c4 + 1][slot0_row] = tf32rf(b0.y);
        Bs[0][slot0_c4 + 2][slot0_row] = tf32rf(b0.z);
        Bs[0][slot0_c4 + 3][slot0_row] = tf32rf(b0.w);
        Bs[0][slot1_c4 + 0][slot1_row] = tf32rf(b1.x);
        Bs[0][slot1_c4 + 1][slot1_row] = tf32rf(b1.y);
        Bs[0][slot1_c4 + 2][slot1_row] = tf32rf(b1.z);
        Bs[0][slot1_c4 + 3][slot1_row] = tf32rf(b1.w);
    }
    __syncthreads();

    const int NCH = EMB / BKC;

#pragma unroll 1
    for (int c = 0; c < NCH; c++) {
        const int buf = c & 1;

        float4 a0, a1, b0, b1;
        const bool more = (c + 1 < NCH);
        if (more) {
            const int k0 = (c + 1) * BKC;
            a0 = *reinterpret_cast<const float4*>(Ap + (size_t)slot0_row * EMB + k0 + slot0_c4);
            a1 = *reinterpret_cast<const float4*>(Ap + (size_t)slot1_row * EMB + k0 + slot1_c4);
            b0 = *reinterpret_cast<const float4*>(Wp + (size_t)slot0_row * EMB + k0 + slot0_c4);
            b1 = *reinterpret_cast<const float4*>(Wp + (size_t)slot1_row * EMB + k0 + slot1_c4);
        }

#pragma unroll
        for (int ks = 0; ks < 2; ks++) {
            const int kk = ks * 8;
            uint32_t afr[4][4], bfr[4][2];
#pragma unroll
            for (int mf = 0; mf < 4; mf++) {
                const int m0 = wm * 64 + mf * 16 + gID;
                afr[mf][0] = __float_as_uint(As[buf][kk + tig][m0]);
                afr[mf][1] = __float_as_uint(As[buf][kk + tig][m0 + 8]);
                afr[mf][2] = __float_as_uint(As[buf][kk + tig + 4][m0]);
                afr[mf][3] = __float_as_uint(As[buf][kk + tig + 4][m0 + 8]);
            }
#pragma unroll
            for (int nf = 0; nf < 4; nf++) {
                const int n0 = wn * 32 + nf * 8 + gID;
                bfr[nf][0] = __float_as_uint(Bs[buf][kk + tig][n0]);
                bfr[nf][1] = __float_as_uint(Bs[buf][kk + tig + 4][n0]);
            }
#pragma unroll
            for (int mf = 0; mf < 4; mf++)
#pragma unroll
                for (int nf = 0; nf < 4; nf++)
                    MMA_TF32(acc[mf][nf], afr[mf], bfr[nf]);
        }

        if (more) {
            const int ob = buf ^ 1;
            As[ob][slot0_c4 + 0][slot0_row] = tf32rf(a0.x);
            As[ob][slot0_c4 + 1][slot0_row] = tf32rf(a0.y);
            As[ob][slot0_c4 + 2][slot0_row] = tf32rf(a0.z);
            As[ob][slot0_c4 + 3][slot0_row] = tf32rf(a0.w);
            As[ob][slot1_c4 + 0][slot1_row] = tf32rf(a1.x);
            As[ob][slot1_c4 + 1][slot1_row] = tf32rf(a1.y);
            As[ob][slot1_c4 + 2][slot1_row] = tf32rf(a1.z);
            As[ob][slot1_c4 + 3][slot1_row] = tf32rf(a1.w);
            Bs[ob][slot0_c4 + 0][slot0_row] = tf32rf(b0.x);
            Bs[ob][slot0_c4 + 1][slot0_row] = tf32rf(b0.y);
            Bs[ob][slot0_c4 + 2][slot0_row] = tf32rf(b0.z);
            Bs[ob][slot0_c4 + 3][slot0_row] = tf32rf(b0.w);
            Bs[ob][slot1_c4 + 0][slot1_row] = tf32rf(b1.x);
            Bs[ob][slot1_c4 + 1][slot1_row] = tf32rf(b1.y);
            Bs[ob][slot1_c4 + 2][slot1_row] = tf32rf(b1.z);
            Bs[ob][slot1_c4 + 3][slot1_row] = tf32rf(b1.w);
        }
        __syncthreads();
    }

#pragma unroll
    for (int mf = 0; mf < 4; mf++) {
#pragma unroll
        for (int nf = 0; nf < 4; nf++) {
            const int r0 = bm + wm * 64 + mf * 16 + gID;
            const int r1 = r0 + 8;
            const int cc = bn + wn * 32 + nf * 8 + tig * 2;
            const float bi0 = bias[cc];
            const float bi1 = bias[cc + 1];
            float2 v0 = make_float2(acc[mf][nf][0] + bi0, acc[mf][nf][1] + bi1);
            float2 v1 = make_float2(acc[mf][nf][2] + bi0, acc[mf][nf][3] + bi1);
            if (LAYOUT == 0) {
                *reinterpret_cast<float2*>(C + (size_t)r0 * EMB + cc) = v0;
                *reinterpret_cast<float2*>(C + (size_t)r1 * EMB + cc) = v1;
            } else {
                const int hh = cc >> 6;
                const int dd = cc & 63;
                {
                    const int bb = r0 >> 11, ss = r0 & 2047;
                    *reinterpret_cast<float2*>(
                        C + (((size_t)(bb * NHEAD + hh) << 11) + ss) * HDIM + dd) = v0;
                }
                {
                    const int bb = r1 >> 11, ss = r1 & 2047;
                    *reinterpret_cast<float2*>(
                        C + (((size_t)(bb * NHEAD + hh) << 11) + ss) * HDIM + dd) = v1;
                }
            }
        }
    }
}

// ---------------------------------------------------------------------------
// tf32 mma.sync causal flash attention.
// CTA: 64 q-rows x 64 k-tile, 4 warps (16 q-rows each). Q/K/V in (B*H,S,D).
// Softmax in base-2 domain (scale*log2e folded into Q); exp2 on the FMA pipe.
// smem (dynamic): Qs[64][68], Ks[64][68], Vs[64][72], Ps[64][68]  = 70656 B.
// Output written to (B, S, H*D) for the final GEMM.
// ---------------------------------------------------------------------------
#define SQ 68
#define SKS 68
#define SV 72
#define SP 68
#define ATTN_SMEM ((64*SQ + 64*SKS + 64*SV + 64*SP) * 4)   // 70656 bytes

__global__ __launch_bounds__(128, 3)
void attn_mma(const float* __restrict__ Q,
              const float* __restrict__ K,
              const float* __restrict__ V,
              float* __restrict__ O)
{
    extern __shared__ float sm[];
    float* Qs = sm;                       // [64][SQ]
    float* Ks = sm + 64 * SQ;             // [64][SKS]
    float* Vs = Ks + 64 * SKS;            // [64][SV]
    float* Ps = Vs + 64 * SV;             // [64][SP]

    const int tid  = threadIdx.x;
    const int lane = tid & 31;
    const int wid  = tid >> 5;            // 0..3
    const int g    = lane >> 2;           // 0..7
    const int tig  = lane & 3;            // 0..3
    const int m0   = wid * 16;

    const int bh = blockIdx.y;
    const int qt = (int)gridDim.x - 1 - (int)blockIdx.x;   // heavy tiles first
    const int q0 = qt << 6;

    const float* qp = Q + (size_t)bh * S_LEN * HDIM;
    const float* kp = K + (size_t)bh * S_LEN * HDIM;
    const float* vp = V + (size_t)bh * S_LEN * HDIM;

    const float QSCALE = 0.125f * 1.4426950408889634f;   // sm_scale * log2(e)

    const int row0 = tid >> 4;            // 0..7
    const int c4   = (tid & 15) << 2;     // 0..60

    // Load Q tile (scaled + tf32-rounded), natural layout
#pragma unroll
    for (int i = 0; i < 8; i++) {
        const int r = row0 + i * 8;
        float4 v = *reinterpret_cast<const float4*>(qp + (size_t)(q0 + r) * HDIM + c4);
        float4 o;
        o.x = tf32rf(v.x * QSCALE); o.y = tf32rf(v.y * QSCALE);
        o.z = tf32rf(v.z * QSCALE); o.w = tf32rf(v.w * QSCALE);
        *reinterpret_cast<float4*>(&Qs[r * SQ + c4]) = o;
    }

    float mr[2] = {-1e30f, -1e30f};
    float lr[2] = {0.f, 0.f};
    float oacc[8][4];
#pragma unroll
    for (int nf = 0; nf < 8; nf++)
#pragma unroll
        for (int r = 0; r < 4; r++) oacc[nf][r] = 0.f;

#pragma unroll 1
    for (int kt = 0; kt <= qt; kt++) {
        const int k0 = kt << 6;
        __syncthreads();   // previous PV reads of Ks/Vs done (and Q load on iter 0)

        // Load K, V tiles (tf32-rounded), natural layout
#pragma unroll
        for (int i = 0; i < 8; i++) {
            const int r = row0 + i * 8;
            float4 kv = *reinterpret_cast<const float4*>(kp + (size_t)(k0 + r) * HDIM + c4);
            float4 ko;
            ko.x = tf32rf(kv.x); ko.y = tf32rf(kv.y);
            ko.z = tf32rf(kv.z); ko.w = tf32rf(kv.w);
            *reinterpret_cast<float4*>(&Ks[r * SKS + c4]) = ko;
            float4 vv = *reinterpret_cast<const float4*>(vp + (size_t)(k0 + r) * HDIM + c4);
            float4 vo;
            vo.x = tf32rf(vv.x); vo.y = tf32rf(vv.y);
            vo.z = tf32rf(vv.z); vo.w = tf32rf(vv.w);
            *reinterpret_cast<float4*>(&Vs[r * SV + c4]) = vo;
        }
        __syncthreads();

        // ---- S2 = (scaled Q) @ K^T : m16 x n64, 8 k-steps ----
        float s[8][4];
#pragma unroll
        for (int nf = 0; nf < 8; nf++)
#pragma unroll
            for (int r = 0; r < 4; r++) s[nf][r] = 0.f;

#pragma unroll
        for (int ks = 0; ks < 8; ks++) {
            const int kk = ks * 8;
            uint32_t a[4];
            a[0] = __float_as_uint(Qs[(m0 + g) * SQ + kk + tig]);
            a[1] = __float_as_uint(Qs[(m0 + g + 8) * SQ + kk + tig]);
            a[2] = __float_as_uint(Qs[(m0 + g) * SQ + kk + tig + 4]);
            a[3] = __float_as_uint(Qs[(m0 + g + 8) * SQ + kk + tig + 4]);
#pragma unroll
            for (int nf = 0; nf < 8; nf++) {
                uint32_t b[2];
                b[0] = __float_as_uint(Ks[(nf * 8 + g) * SKS + kk + tig]);
                b[1] = __float_as_uint(Ks[(nf * 8 + g) * SKS + kk + tig + 4]);
                MMA_TF32(s[nf], a, b);
            }
        }

        // ---- causal mask on the diagonal tile (k0 == q0) ----
        if (kt == qt) {
            const int r0l = m0 + g;
            const int r1l = r0l + 8;
#pragma unroll
            for (int nf = 0; nf < 8; nf++) {
                const int c0 = nf * 8 + 2 * tig;
                if (c0     > r0l) s[nf][0] = -1e30f;
                if (c0 + 1 > r0l) s[nf][1] = -1e30f;
                if (c0     > r1l) s[nf][2] = -1e30f;
                if (c0 + 1 > r1l) s[nf][3] = -1e30f;
            }
        }

        // ---- online softmax (base-2), exp on FMA pipe ----
#pragma unroll
        for (int r = 0; r < 2; r++) {
            float mx = -1e30f;
#pragma unroll
            for (int nf = 0; nf < 8; nf++)
                mx = fmaxf(mx, fmaxf(s[nf][2 * r], s[nf][2 * r + 1]));
            mx = fmaxf(mx, __shfl_xor_sync(0xffffffffu, mx, 1));
            mx = fmaxf(mx, __shfl_xor_sync(0xffffffffu, mx, 2));

            const float mnew = fmaxf(mr[r], mx);
            const float resc = exp2_poly(mr[r] - mnew);
            mr[r] = mnew;

            float sum = 0.f;
#pragma unroll
            for (int nf = 0; nf < 8; nf++) {
#pragma unroll
                for (int u = 0; u < 2; u++) {
                    float p = exp2_poly(s[nf][2 * r + u] - mnew);
                    p = __uint_as_float(__float_as_uint(p) & 0xFFFFE000u);  // tf32 trunc
                    s[nf][2 * r + u] = p;
                    sum += p;
                }
            }
            sum += __shfl_xor_sync(0xffffffffu, sum, 1);
            sum += __shfl_xor_sync(0xffffffffu, sum, 2);

            lr[r] = lr[r] * resc + sum;
#pragma unroll
            for (int nf = 0; nf < 8; nf++) {
                oacc[nf][2 * r]     *= resc;
                oacc[nf][2 * r + 1] *= resc;
            }
        }

        // ---- write P to (warp-private) smem region ----
#pragma unroll
        for (int nf = 0; nf < 8; nf++) {
#pragma unroll
            for (int r = 0; r < 2; r++) {
                float2 pv = make_float2(s[nf][2 * r], s[nf][2 * r + 1]);
                *reinterpret_cast<float2*>(&Ps[(m0 + g + 8 * r) * SP + nf * 8 + 2 * tig]) = pv;
            }
        }
        __syncwarp();

        // ---- O += P @ V : m16 x n64(d), 8 k-steps over keys ----
#pragma unroll
        for (int ks = 0; ks < 8; ks++) {
            const int kk = ks * 8;
            uint32_t a[4];
            a[0] = __float_as_uint(Ps[(m0 + g) * SP + kk + tig]);
            a[1] = __float_as_uint(Ps[(m0 + g + 8) * SP + kk + tig]);
            a[2] = __float_as_uint(Ps[(m0 + g) * SP + kk + tig + 4]);
            a[3] = __float_as_uint(Ps[(m0 + g + 8) * SP + kk + tig + 4]);
#pragma unroll
            for (int nf = 0; nf < 8; nf++) {
                uint32_t b[2];
                b[0] = __float_as_uint(Vs[(kk + tig) * SV + nf * 8 + g]);
                b[1] = __float_as_uint(Vs[(kk + tig + 4) * SV + nf * 8 + g]);
                MMA_TF32(oacc[nf], a, b);
            }
        }
    }

    // ---- finalize: divide by l, write (B, S, H*D) ----
    const int b = bh >> 4;
    const int h = bh & 15;
    const float inv0 = 1.f / lr[0];
    const float inv1 = 1.f / lr[1];
    float* ob = O + ((size_t)(b * S_LEN + q0 + m0 + g)) * EMB + h * HDIM + 2 * tig;
#pragma unroll
    for (int nf = 0; nf < 8; nf++) {
        float2 v0 = make_float2(oacc[nf][0] * inv0, oacc[nf][1] * inv0);
        float2 v1 = make_float2(oacc[nf][2] * inv1, oacc[nf][3] * inv1);
        *reinterpret_cast<float2*>(ob + nf * 8)                     = v0;
        *reinterpret_cast<float2*>(ob + (size_t)8 * EMB + nf * 8)   = v1;
    }
}

// ---------------------------------------------------------------------------
// Launcher
// ---------------------------------------------------------------------------
extern "C" void kernel_launch(void* const* d_in, const int* in_sizes, int n_in,
                              void* d_out, int out_size)
{
    const float* x  = (const float*)d_in[0];
    const float* Wq = (const float*)d_in[1];
    const float* bq = (const float*)d_in[2];
    const float* Wk = (const float*)d_in[3];
    const float* bk = (const float*)d_in[4];
    const float* Wv = (const float*)d_in[5];
    const float* bv = (const float*)d_in[6];
    const float* Wo = (const float*)d_in[7];
    const float* bo = (const float*)d_in[8];
    float* out = (float*)d_out;

    float *q, *k, *v, *attn;
    cudaGetSymbolAddress((void**)&q,    g_q);
    cudaGetSymbolAddress((void**)&k,    g_k);
    cudaGetSymbolAddress((void**)&v,    g_v);
    cudaGetSymbolAddress((void**)&attn, g_attn);

    cudaFuncSetAttribute(attn_mma, cudaFuncAttributeMaxDynamicSharedMemorySize, ATTN_SMEM);

    dim3 gg(EMB / 128, MROWS / 128);   // (8, 32)
    gemm_mma<1><<<gg, 256>>>(x, Wq, bq, q);
    gemm_mma<1><<<gg, 256>>>(x, Wk, bk, k);
    gemm_mma<1><<<gg, 256>>>(x, Wv, bv, v);

    dim3 ga(S_LEN / 64, BATCH * NHEAD);   // (32, 32)
    attn_mma<<<ga, 128, ATTN_SMEM>>>(q, k, v, attn);

    gemm_mma<0><<<gg, 256>>>(attn, Wo, bo, out);
}

// round 5
// speedup vs baseline: 2.7511x; 1.0056x over previous
#include <cuda_runtime.h>
#include <cstdint>

// ---------------------------------------------------------------------------
// Problem constants
// ---------------------------------------------------------------------------
#define S_LEN  2048
#define NHEAD  16
#define HDIM   64
#define BATCH  2
#define EMB    1024
#define MROWS  (BATCH * S_LEN)   // 4096

// ---------------------------------------------------------------------------
// Scratch (allocation-free rule: __device__ globals)
// ---------------------------------------------------------------------------
__device__ __align__(16) float g_q[(size_t)MROWS * EMB];
__device__ __align__(16) float g_k[(size_t)MROWS * EMB];
__device__ __align__(16) float g_v[(size_t)MROWS * EMB];
__device__ __align__(16) float g_attn[(size_t)MROWS * EMB];

// ---------------------------------------------------------------------------
// tf32 helpers (base ISA, sm_80+)
// ---------------------------------------------------------------------------
__device__ __forceinline__ uint32_t tf32r(float x) {   // round-to-nearest tf32
    uint32_t o;
    asm("cvt.rna.tf32.f32 %0, %1;" : "=r"(o) : "f"(x));
    return o;
}
__device__ __forceinline__ float tf32rf(float x) { return __uint_as_float(tf32r(x)); }

#define MMA_TF32(d, a, b)                                                   \
    asm volatile("mma.sync.aligned.m16n8k8.row.col.f32.tf32.tf32.f32 "      \
        "{%0,%1,%2,%3}, {%4,%5,%6,%7}, {%8,%9}, {%0,%1,%2,%3};"             \
        : "+f"((d)[0]), "+f"((d)[1]), "+f"((d)[2]), "+f"((d)[3])            \
        : "r"((a)[0]), "r"((a)[1]), "r"((a)[2]), "r"((a)[3]),               \
          "r"((b)[0]), "r"((b)[1]))

// exp2 on the FMA pipe: no MUFU, no CVT. x must be <= 0.
__device__ __forceinline__ float exp2_poly(float x) {
    x = fmaxf(x, -126.f);
    float y = x + 12582912.f;              // 1.5 * 2^23  (round-to-nearest int)
    int   iy = __float_as_int(y);
    float n  = y - 12582912.f;
    float f  = x - n;                      // f in [-0.5, 0.5]
    float p  = 0.0013333558f;
    p = fmaf(p, f, 0.0096181291f);
    p = fmaf(p, f, 0.0555041086f);
    p = fmaf(p, f, 0.2402265069f);
    p = fmaf(p, f, 0.6931471806f);
    p = fmaf(p, f, 1.0f);
    return __int_as_float((iy + 127) << 23) * p;   // 2^n * poly(f)
}

// ---------------------------------------------------------------------------
// tf32 mma.sync GEMM v2:  C(MxN) = A(MxK) @ W^T(NxK) + bias
// CTA tile 128(M) x 256(N), 8 warps (2M x 4N), warp tile 64x64, BK=16,
// double-buffered dynamic smem. Strides ≡ 8 (mod 32) -> conflict-free
// fragment LDS (bank = 8*tig + g) AND conflict-free STS (32 consecutive
// rows per store instruction).
// LAYOUT 0: plain row-major.  LAYOUT 1: head-split (B,H,S,D).
// ---------------------------------------------------------------------------
#define BKC 16
#define SA  136                     // As row stride (floats), 136 % 32 == 8
#define SB  264                     // Bs row stride (floats), 264 % 32 == 8
#define GEMM_SMEM ((2 * BKC * SA + 2 * BKC * SB) * 4)   // 51200 bytes

template <int LAYOUT>
__global__ __launch_bounds__(256, 1)
void gemm_mma(const float* __restrict__ A,
              const float* __restrict__ W,
              const float* __restrict__ bias,
              float* __restrict__ C)
{
    extern __shared__ float sm[];
    float* As = sm;                         // [2][BKC][SA]
    float* Bs = sm + 2 * BKC * SA;          // [2][BKC][SB]

    const int tid  = threadIdx.x;
    const int lane = tid & 31;
    const int wid  = tid >> 5;
    const int g    = lane >> 2;   // 0..7
    const int tig  = lane & 3;    // 0..3
    const int wm   = wid >> 2;    // 0..1  (M, 64 rows each)
    const int wn   = wid & 3;     // 0..3  (N, 64 cols each)
    const int bm   = blockIdx.y * 128;
    const int bn   = blockIdx.x * 256;

    // Global load mapping (one row per lane -> conflict-free STS):
    // A tile 128x16: row = tid & 127, two float4 at k = ac4, ac4+4
    const int arow = tid & 127;
    const int ac4  = (tid >> 7) * 8;
    // B tile 256x16: row = tid, four float4 at k = 0,4,8,12
    const int brow = tid;

    const float* Ap = A + (size_t)(bm + arow) * EMB + ac4;
    const float* Wp = W + (size_t)(bn + brow) * EMB;

    float acc[4][8][4];
#pragma unroll
    for (int mf = 0; mf < 4; mf++)
#pragma unroll
        for (int nf = 0; nf < 8; nf++)
#pragma unroll
            for (int r = 0; r < 4; r++) acc[mf][nf][r] = 0.f;

    // ---- prologue: chunk 0 -> buffer 0 ----
    {
        float4 a0 = *reinterpret_cast<const float4*>(Ap);
        float4 a1 = *reinterpret_cast<const float4*>(Ap + 4);
        float4 b0 = *reinterpret_cast<const float4*>(Wp + 0);
        float4 b1 = *reinterpret_cast<const float4*>(Wp + 4);
        float4 b2 = *reinterpret_cast<const float4*>(Wp + 8);
        float4 b3 = *reinterpret_cast<const float4*>(Wp + 12);
        As[(ac4 + 0) * SA + arow] = tf32rf(a0.x);
        As[(ac4 + 1) * SA + arow] = tf32rf(a0.y);
        As[(ac4 + 2) * SA + arow] = tf32rf(a0.z);
        As[(ac4 + 3) * SA + arow] = tf32rf(a0.w);
        As[(ac4 + 4) * SA + arow] = tf32rf(a1.x);
        As[(ac4 + 5) * SA + arow] = tf32rf(a1.y);
        As[(ac4 + 6) * SA + arow] = tf32rf(a1.z);
        As[(ac4 + 7) * SA + arow] = tf32rf(a1.w);
        Bs[ 0 * SB + brow] = tf32rf(b0.x);
        Bs[ 1 * SB + brow] = tf32rf(b0.y);
        Bs[ 2 * SB + brow] = tf32rf(b0.z);
        Bs[ 3 * SB + brow] = tf32rf(b0.w);
        Bs[ 4 * SB + brow] = tf32rf(b1.x);
        Bs[ 5 * SB + brow] = tf32rf(b1.y);
        Bs[ 6 * SB + brow] = tf32rf(b1.z);
        Bs[ 7 * SB + brow] = tf32rf(b1.w);
        Bs[ 8 * SB + brow] = tf32rf(b2.x);
        Bs[ 9 * SB + brow] = tf32rf(b2.y);
        Bs[10 * SB + brow] = tf32rf(b2.z);
        Bs[11 * SB + brow] = tf32rf(b2.w);
        Bs[12 * SB + brow] = tf32rf(b3.x);
        Bs[13 * SB + brow] = tf32rf(b3.y);
        Bs[14 * SB + brow] = tf32rf(b3.z);
        Bs[15 * SB + brow] = tf32rf(b3.w);
    }
    __syncthreads();

    const int NCH = EMB / BKC;   // 64

#pragma unroll 1
    for (int c = 0; c < NCH; c++) {
        const int buf = c & 1;
        float* Ab = As + buf * BKC * SA;
        float* Bb = Bs + buf * BKC * SB;

        // Stage next chunk's globals into registers (overlaps MMAs)
        float4 a0, a1, b0, b1, b2, b3;
        const bool more = (c + 1 < NCH);
        if (more) {
            const int k0 = (c + 1) * BKC;
            a0 = *reinterpret_cast<const float4*>(Ap + k0);
            a1 = *reinterpret_cast<const float4*>(Ap + k0 + 4);
            b0 = *reinterpret_cast<const float4*>(Wp + k0 + 0);
            b1 = *reinterpret_cast<const float4*>(Wp + k0 + 4);
            b2 = *reinterpret_cast<const float4*>(Wp + k0 + 8);
            b3 = *reinterpret_cast<const float4*>(Wp + k0 + 12);
        }

        // Compute on buf
#pragma unroll
        for (int ks = 0; ks < 2; ks++) {
            const int kk = ks * 8;
            uint32_t afr[4][4], bfr[8][2];
#pragma unroll
            for (int mf = 0; mf < 4; mf++) {
                const int m0 = wm * 64 + mf * 16 + g;
                afr[mf][0] = __float_as_uint(Ab[(kk + tig) * SA + m0]);
                afr[mf][1] = __float_as_uint(Ab[(kk + tig) * SA + m0 + 8]);
                afr[mf][2] = __float_as_uint(Ab[(kk + tig + 4) * SA + m0]);
                afr[mf][3] = __float_as_uint(Ab[(kk + tig + 4) * SA + m0 + 8]);
            }
#pragma unroll
            for (int nf = 0; nf < 8; nf++) {
                const int n0 = wn * 64 + nf * 8 + g;
                bfr[nf][0] = __float_as_uint(Bb[(kk + tig) * SB + n0]);
                bfr[nf][1] = __float_as_uint(Bb[(kk + tig + 4) * SB + n0]);
            }
#pragma unroll
            for (int mf = 0; mf < 4; mf++)
#pragma unroll
                for (int nf = 0; nf < 8; nf++)
                    MMA_TF32(acc[mf][nf], afr[mf], bfr[nf]);
        }

        // Store staged chunk into the other buffer
        if (more) {
            float* Ao = As + (buf ^ 1) * BKC * SA;
            float* Bo = Bs + (buf ^ 1) * BKC * SB;
            Ao[(ac4 + 0) * SA + arow] = tf32rf(a0.x);
            Ao[(ac4 + 1) * SA + arow] = tf32rf(a0.y);
            Ao[(ac4 + 2) * SA + arow] = tf32rf(a0.z);
            Ao[(ac4 + 3) * SA + arow] = tf32rf(a0.w);
            Ao[(ac4 + 4) * SA + arow] = tf32rf(a1.x);
            Ao[(ac4 + 5) * SA + arow] = tf32rf(a1.y);
            Ao[(ac4 + 6) * SA + arow] = tf32rf(a1.z);
            Ao[(ac4 + 7) * SA + arow] = tf32rf(a1.w);
            Bo[ 0 * SB + brow] = tf32rf(b0.x);
            Bo[ 1 * SB + brow] = tf32rf(b0.y);
            Bo[ 2 * SB + brow] = tf32rf(b0.z);
            Bo[ 3 * SB + brow] = tf32rf(b0.w);
            Bo[ 4 * SB + brow] = tf32rf(b1.x);
            Bo[ 5 * SB + brow] = tf32rf(b1.y);
            Bo[ 6 * SB + brow] = tf32rf(b1.z);
            Bo[ 7 * SB + brow] = tf32rf(b1.w);
            Bo[ 8 * SB + brow] = tf32rf(b2.x);
            Bo[ 9 * SB + brow] = tf32rf(b2.y);
            Bo[10 * SB + brow] = tf32rf(b2.z);
            Bo[11 * SB + brow] = tf32rf(b2.w);
            Bo[12 * SB + brow] = tf32rf(b3.x);
            Bo[13 * SB + brow] = tf32rf(b3.y);
            Bo[14 * SB + brow] = tf32rf(b3.z);
            Bo[15 * SB + brow] = tf32rf(b3.w);
        }
        __syncthreads();
    }

    // Epilogue: bias + layout remap, float2 stores
#pragma unroll
    for (int mf = 0; mf < 4; mf++) {
#pragma unroll
        for (int nf = 0; nf < 8; nf++) {
            const int r0 = bm + wm * 64 + mf * 16 + g;
            const int r1 = r0 + 8;
            const int cc = bn + wn * 64 + nf * 8 + tig * 2;
            const float bi0 = bias[cc];
            const float bi1 = bias[cc + 1];
            float2 v0 = make_float2(acc[mf][nf][0] + bi0, acc[mf][nf][1] + bi1);
            float2 v1 = make_float2(acc[mf][nf][2] + bi0, acc[mf][nf][3] + bi1);
            if (LAYOUT == 0) {
                *reinterpret_cast<float2*>(C + (size_t)r0 * EMB + cc) = v0;
                *reinterpret_cast<float2*>(C + (size_t)r1 * EMB + cc) = v1;
            } else {
                const int hh = cc >> 6;
                const int dd = cc & 63;
                {
                    const int bb = r0 >> 11, ss = r0 & 2047;
                    *reinterpret_cast<float2*>(
                        C + (((size_t)(bb * NHEAD + hh) << 11) + ss) * HDIM + dd) = v0;
                }
                {
                    const int bb = r1 >> 11, ss = r1 & 2047;
                    *reinterpret_cast<float2*>(
                        C + (((size_t)(bb * NHEAD + hh) << 11) + ss) * HDIM + dd) = v1;
                }
            }
        }
    }
}

// ---------------------------------------------------------------------------
// tf32 mma.sync causal flash attention (unchanged from R4 — proven).
// ---------------------------------------------------------------------------
#define SQ 68
#define SKS 68
#define SV 72
#define SP 68
#define ATTN_SMEM ((64*SQ + 64*SKS + 64*SV + 64*SP) * 4)   // 70656 bytes

__global__ __launch_bounds__(128, 3)
void attn_mma(const float* __restrict__ Q,
              const float* __restrict__ K,
              const float* __restrict__ V,
              float* __restrict__ O)
{
    extern __shared__ float sm[];
    float* Qs = sm;                       // [64][SQ]
    float* Ks = sm + 64 * SQ;             // [64][SKS]
    float* Vs = Ks + 64 * SKS;            // [64][SV]
    float* Ps = Vs + 64 * SV;             // [64][SP]

    const int tid  = threadIdx.x;
    const int lane = tid & 31;
    const int wid  = tid >> 5;            // 0..3
    const int g    = lane >> 2;           // 0..7
    const int tig  = lane & 3;            // 0..3
    const int m0   = wid * 16;

    const int bh = blockIdx.y;
    const int qt = (int)gridDim.x - 1 - (int)blockIdx.x;   // heavy tiles first
    const int q0 = qt << 6;

    const float* qp = Q + (size_t)bh * S_LEN * HDIM;
    const float* kp = K + (size_t)bh * S_LEN * HDIM;
    const float* vp = V + (size_t)bh * S_LEN * HDIM;

    const float QSCALE = 0.125f * 1.4426950408889634f;   // sm_scale * log2(e)

    const int row0 = tid >> 4;            // 0..7
    const int c4   = (tid & 15) << 2;     // 0..60

#pragma unroll
    for (int i = 0; i < 8; i++) {
        const int r = row0 + i * 8;
        float4 v = *reinterpret_cast<const float4*>(qp + (size_t)(q0 + r) * HDIM + c4);
        float4 o;
        o.x = tf32rf(v.x * QSCALE); o.y = tf32rf(v.y * QSCALE);
        o.z = tf32rf(v.z * QSCALE); o.w = tf32rf(v.w * QSCALE);
        *reinterpret_cast<float4*>(&Qs[r * SQ + c4]) = o;
    }

    float mr[2] = {-1e30f, -1e30f};
    float lr[2] = {0.f, 0.f};
    float oacc[8][4];
#pragma unroll
    for (int nf = 0; nf < 8; nf++)
#pragma unroll
        for (int r = 0; r < 4; r++) oacc[nf][r] = 0.f;

#pragma unroll 1
    for (int kt = 0; kt <= qt; kt++) {
        const int k0 = kt << 6;
        __syncthreads();

#pragma unroll
        for (int i = 0; i < 8; i++) {
            const int r = row0 + i * 8;
            float4 kv = *reinterpret_cast<const float4*>(kp + (size_t)(k0 + r) * HDIM + c4);
            float4 ko;
            ko.x = tf32rf(kv.x); ko.y = tf32rf(kv.y);
            ko.z = tf32rf(kv.z); ko.w = tf32rf(kv.w);
            *reinterpret_cast<float4*>(&Ks[r * SKS + c4]) = ko;
            float4 vv = *reinterpret_cast<const float4*>(vp + (size_t)(k0 + r) * HDIM + c4);
            float4 vo;
            vo.x = tf32rf(vv.x); vo.y = tf32rf(vv.y);
            vo.z = tf32rf(vv.z); vo.w = tf32rf(vv.w);
            *reinterpret_cast<float4*>(&Vs[r * SV + c4]) = vo;
        }
        __syncthreads();

        float s[8][4];
#pragma unroll
        for (int nf = 0; nf < 8; nf++)
#pragma unroll
            for (int r = 0; r < 4; r++) s[nf][r] = 0.f;

#pragma unroll
        for (int ks = 0; ks < 8; ks++) {
            const int kk = ks * 8;
            uint32_t a[4];
            a[0] = __float_as_uint(Qs[(m0 + g) * SQ + kk + tig]);
            a[1] = __float_as_uint(Qs[(m0 + g + 8) * SQ + kk + tig]);
            a[2] = __float_as_uint(Qs[(m0 + g) * SQ + kk + tig + 4]);
            a[3] = __float_as_uint(Qs[(m0 + g + 8) * SQ + kk + tig + 4]);
#pragma unroll
            for (int nf = 0; nf < 8; nf++) {
                uint32_t b[2];
                b[0] = __float_as_uint(Ks[(nf * 8 + g) * SKS + kk + tig]);
                b[1] = __float_as_uint(Ks[(nf * 8 + g) * SKS + kk + tig + 4]);
                MMA_TF32(s[nf], a, b);
            }
        }

        if (kt == qt) {
            const int r0l = m0 + g;
            const int r1l = r0l + 8;
#pragma unroll
            for (int nf = 0; nf < 8; nf++) {
                const int c0 = nf * 8 + 2 * tig;
                if (c0     > r0l) s[nf][0] = -1e30f;
                if (c0 + 1 > r0l) s[nf][1] = -1e30f;
                if (c0     > r1l) s[nf][2] = -1e30f;
                if (c0 + 1 > r1l) s[nf][3] = -1e30f;
            }
        }

#pragma unroll
        for (int r = 0; r < 2; r++) {
            float mx = -1e30f;
#pragma unroll
            for (int nf = 0; nf < 8; nf++)
                mx = fmaxf(mx, fmaxf(s[nf][2 * r], s[nf][2 * r + 1]));
            mx = fmaxf(mx, __shfl_xor_sync(0xffffffffu, mx, 1));
            mx = fmaxf(mx, __shfl_xor_sync(0xffffffffu, mx, 2));

            const float mnew = fmaxf(mr[r], mx);
            const float resc = exp2_poly(mr[r] - mnew);
            mr[r] = mnew;

            float sum = 0.f;
#pragma unroll
            for (int nf = 0; nf < 8; nf++) {
#pragma unroll
                for (int u = 0; u < 2; u++) {
                    float p = exp2_poly(s[nf][2 * r + u] - mnew);
                    p = __uint_as_float(__float_as_uint(p) & 0xFFFFE000u);  // tf32 trunc
                    s[nf][2 * r + u] = p;
                    sum += p;
                }
            }
            sum += __shfl_xor_sync(0xffffffffu, sum, 1);
            sum += __shfl_xor_sync(0xffffffffu, sum, 2);

            lr[r] = lr[r] * resc + sum;
#pragma unroll
            for (int nf = 0; nf < 8; nf++) {
                oacc[nf][2 * r]     *= resc;
                oacc[nf][2 * r + 1] *= resc;
            }
        }

#pragma unroll
        for (int nf = 0; nf < 8; nf++) {
#pragma unroll
            for (int r = 0; r < 2; r++) {
                float2 pv = make_float2(s[nf][2 * r], s[nf][2 * r + 1]);
                *reinterpret_cast<float2*>(&Ps[(m0 + g + 8 * r) * SP + nf * 8 + 2 * tig]) = pv;
            }
        }
        __syncwarp();

#pragma unroll
        for (int ks = 0; ks < 8; ks++) {
            const int kk = ks * 8;
            uint32_t a[4];
            a[0] = __float_as_uint(Ps[(m0 + g) * SP + kk + tig]);
            a[1] = __float_as_uint(Ps[(m0 + g + 8) * SP + kk + tig]);
            a[2] = __float_as_uint(Ps[(m0 + g) * SP + kk + tig + 4]);
            a[3] = __float_as_uint(Ps[(m0 + g + 8) * SP + kk + tig + 4]);
#pragma unroll
            for (int nf = 0; nf < 8; nf++) {
                uint32_t b[2];
                b[0] = __float_as_uint(Vs[(kk + tig) * SV + nf * 8 + g]);
                b[1] = __float_as_uint(Vs[(kk + tig + 4) * SV + nf * 8 + g]);
                MMA_TF32(oacc[nf], a, b);
            }
        }
    }

    const int b = bh >> 4;
    const int h = bh & 15;
    const float inv0 = 1.f / lr[0];
    const float inv1 = 1.f / lr[1];
    float* ob = O + ((size_t)(b * S_LEN + q0 + m0 + g)) * EMB + h * HDIM + 2 * tig;
#pragma unroll
    for (int nf = 0; nf < 8; nf++) {
        float2 v0 = make_float2(oacc[nf][0] * inv0, oacc[nf][1] * inv0);
        float2 v1 = make_float2(oacc[nf][2] * inv1, oacc[nf][3] * inv1);
        *reinterpret_cast<float2*>(ob + nf * 8)                     = v0;
        *reinterpret_cast<float2*>(ob + (size_t)8 * EMB + nf * 8)   = v1;
    }
}

// ---------------------------------------------------------------------------
// Launcher
// ---------------------------------------------------------------------------
extern "C" void kernel_launch(void* const* d_in, const int* in_sizes, int n_in,
                              void* d_out, int out_size)
{
    const float* x  = (const float*)d_in[0];
    const float* Wq = (const float*)d_in[1];
    const float* bq = (const float*)d_in[2];
    const float* Wk = (const float*)d_in[3];
    const float* bk = (const float*)d_in[4];
    const float* Wv = (const float*)d_in[5];
    const float* bv = (const float*)d_in[6];
    const float* Wo = (const float*)d_in[7];
    const float* bo = (const float*)d_in[8];
    float* out = (float*)d_out;

    float *q, *k, *v, *attn;
    cudaGetSymbolAddress((void**)&q,    g_q);
    cudaGetSymbolAddress((void**)&k,    g_k);
    cudaGetSymbolAddress((void**)&v,    g_v);
    cudaGetSymbolAddress((void**)&attn, g_attn);

    cudaFuncSetAttribute(gemm_mma<0>, cudaFuncAttributeMaxDynamicSharedMemorySize, GEMM_SMEM);
    cudaFuncSetAttribute(gemm_mma<1>, cudaFuncAttributeMaxDynamicSharedMemorySize, GEMM_SMEM);
    cudaFuncSetAttribute(attn_mma, cudaFuncAttributeMaxDynamicSharedMemorySize, ATTN_SMEM);

    dim3 gg(EMB / 256, MROWS / 128);   // (4, 32)
    gemm_mma<1><<<gg, 256, GEMM_SMEM>>>(x, Wq, bq, q);
    gemm_mma<1><<<gg, 256, GEMM_SMEM>>>(x, Wk, bk, k);
    gemm_mma<1><<<gg, 256, GEMM_SMEM>>>(x, Wv, bv, v);

    dim3 ga(S_LEN / 64, BATCH * NHEAD);   // (32, 32)
    attn_mma<<<ga, 128, ATTN_SMEM>>>(q, k, v, attn);

    gemm_mma<0><<<gg, 256, GEMM_SMEM>>>(attn, Wo, bo, out);
}

// round 6
// speedup vs baseline: 3.1182x; 1.1334x over previous
#include <cuda_runtime.h>
#include <cstdint>

// ---------------------------------------------------------------------------
// Problem constants
// ---------------------------------------------------------------------------
#define S_LEN  2048
#define NHEAD  16
#define HDIM   64
#define BATCH  2
#define EMB    1024
#define MROWS  (BATCH * S_LEN)   // 4096

// ---------------------------------------------------------------------------
// Scratch (allocation-free rule: __device__ globals)
// ---------------------------------------------------------------------------
__device__ __align__(16) float g_q[(size_t)MROWS * EMB];
__device__ __align__(16) float g_k[(size_t)MROWS * EMB];
__device__ __align__(16) float g_v[(size_t)MROWS * EMB];
__device__ __align__(16) float g_attn[(size_t)MROWS * EMB];
__device__ __align__(16) float g_xr[(size_t)MROWS * EMB];     // rounded x
__device__ __align__(16) float g_wq[(size_t)EMB * EMB];       // rounded weights
__device__ __align__(16) float g_wk[(size_t)EMB * EMB];
__device__ __align__(16) float g_wv[(size_t)EMB * EMB];
__device__ __align__(16) float g_wo[(size_t)EMB * EMB];

// ---------------------------------------------------------------------------
// helpers (base ISA, sm_80+)
// ---------------------------------------------------------------------------
__device__ __forceinline__ uint32_t smem_u32(const void* p) {
    uint32_t a;
    asm("{ .reg .u64 t; cvta.to.shared.u64 t, %1; cvt.u32.u64 %0, t; }" : "=r"(a) : "l"(p));
    return a;
}
__device__ __forceinline__ uint32_t tf32r(float x) {   // round-to-nearest tf32
    uint32_t o;
    asm("cvt.rna.tf32.f32 %0, %1;" : "=r"(o) : "f"(x));
    return o;
}
__device__ __forceinline__ float tf32rf(float x) { return __uint_as_float(tf32r(x)); }

#define MMA_TF32(d, a, b)                                                   \
    asm volatile("mma.sync.aligned.m16n8k8.row.col.f32.tf32.tf32.f32 "      \
        "{%0,%1,%2,%3}, {%4,%5,%6,%7}, {%8,%9}, {%0,%1,%2,%3};"             \
        : "+f"((d)[0]), "+f"((d)[1]), "+f"((d)[2]), "+f"((d)[3])            \
        : "r"((a)[0]), "r"((a)[1]), "r"((a)[2]), "r"((a)[3]),               \
          "r"((b)[0]), "r"((b)[1]))

#define CP16(dst, src) \
    asm volatile("cp.async.cg.shared.global [%0], [%1], 16;" :: "r"(dst), "l"(src))
#define CP_COMMIT() asm volatile("cp.async.commit_group;" ::: "memory")
#define CP_WAIT2()  asm volatile("cp.async.wait_group 2;" ::: "memory")

// exp2 on the FMA pipe: no MUFU, no CVT. x must be <= 0.
__device__ __forceinline__ float exp2_poly(float x) {
    x = fmaxf(x, -126.f);
    float y = x + 12582912.f;              // 1.5 * 2^23
    int   iy = __float_as_int(y);
    float n  = y - 12582912.f;
    float f  = x - n;                      // f in [-0.5, 0.5]
    float p  = 0.0013333558f;
    p = fmaf(p, f, 0.0096181291f);
    p = fmaf(p, f, 0.0555041086f);
    p = fmaf(p, f, 0.2402265069f);
    p = fmaf(p, f, 0.6931471806f);
    p = fmaf(p, f, 1.0f);
    return __int_as_float((iy + 127) << 23) * p;
}

// ---------------------------------------------------------------------------
// Pre-round fp32 -> tf32(RN) elementwise (float4 grid-stride)
// ---------------------------------------------------------------------------
__global__ __launch_bounds__(256)
void round_tf32(const float4* __restrict__ in, float4* __restrict__ out, int n4)
{
    int i = blockIdx.x * blockDim.x + threadIdx.x;
    if (i < n4) {
        float4 v = in[i];
        float4 o;
        o.x = tf32rf(v.x); o.y = tf32rf(v.y);
        o.z = tf32rf(v.z); o.w = tf32rf(v.w);
        out[i] = o;
    }
}

// ---------------------------------------------------------------------------
// tf32 mma.sync GEMM v3 (cp.async pipelined, pre-rounded inputs):
//   C(MxN) = A(MxK) @ W^T(NxK) + bias
// CTA 128x128, 8 warps (2M x 4N), warp tile 64x32, BK=16, 4-stage cp.async.
// smem row stride 20 floats -> conflict-free LDS fragments and cp.async STS.
// __launch_bounds__(256,2) -> 2 CTAs/SM for latency hiding.
// LAYOUT 0: plain row-major.  LAYOUT 1: head-split (B,H,S,D).
// ---------------------------------------------------------------------------
#define STAGES 4
#define SROW 20                                 // 16 data + 4 pad floats
#define STAGE_FLOATS (128 * SROW * 2)           // A then B: 5120 floats
#define GEMM_SMEM (STAGES * STAGE_FLOATS * 4)   // 81920 bytes

template <int LAYOUT>
__global__ __launch_bounds__(256, 2)
void gemm_cp(const float* __restrict__ A,     // pre-rounded tf32
             const float* __restrict__ W,     // pre-rounded tf32
             const float* __restrict__ bias,
             float* __restrict__ C)
{
    extern __shared__ float sm[];
    const int tid  = threadIdx.x;
    const int lane = tid & 31;
    const int wid  = tid >> 5;
    const int g    = lane >> 2;   // 0..7
    const int tig  = lane & 3;    // 0..3
    const int wm   = wid >> 2;    // 0..1
    const int wn   = wid & 3;     // 0..3
    const int bm   = blockIdx.y * 128;
    const int bn   = blockIdx.x * 128;

    // cp.async copy mapping: 512 float4 per matrix per stage; 2 rows/thread.
    const int rc0 = tid >> 2;           // 0..63
    const int rc1 = rc0 + 64;           // 64..127
    const int cc4 = (tid & 3) << 2;     // 0,4,8,12

    const float* Ag = A + (size_t)bm * EMB;
    const float* Wg = W + (size_t)bn * EMB;

    const uint32_t sbase = smem_u32(sm);
    const uint32_t offA0 = (uint32_t)(rc0 * SROW + cc4) * 4u;
    const uint32_t offA1 = (uint32_t)(rc1 * SROW + cc4) * 4u;
    const uint32_t offB  = (uint32_t)(128 * SROW) * 4u;

    float acc[4][4][4];
#pragma unroll
    for (int mf = 0; mf < 4; mf++)
#pragma unroll
        for (int nf = 0; nf < 4; nf++)
#pragma unroll
            for (int r = 0; r < 4; r++) acc[mf][nf][r] = 0.f;

    const int NCH = EMB / 16;   // 64

    // prologue: stages 0..2
#pragma unroll
    for (int s = 0; s < 3; s++) {
        const int k0 = s * 16;
        const uint32_t st = sbase + (uint32_t)s * STAGE_FLOATS * 4u;
        CP16(st + offA0,        Ag + (size_t)rc0 * EMB + k0 + cc4);
        CP16(st + offA1,        Ag + (size_t)rc1 * EMB + k0 + cc4);
        CP16(st + offB + offA0, Wg + (size_t)rc0 * EMB + k0 + cc4);
        CP16(st + offB + offA1, Wg + (size_t)rc1 * EMB + k0 + cc4);
        CP_COMMIT();
    }

#pragma unroll 1
    for (int c = 0; c < NCH; c++) {
        CP_WAIT2();            // stage c complete (for this thread's groups)
        __syncthreads();       // all threads' stage-c data visible; stage c-1 reads done

        // issue stage c+3 into slot (c+3)%4 (overwrites stage c-1's buffer)
        if (c + 3 < NCH) {
            const int k0 = (c + 3) * 16;
            const uint32_t st = sbase + (uint32_t)((c + 3) & 3) * STAGE_FLOATS * 4u;
            CP16(st + offA0,        Ag + (size_t)rc0 * EMB + k0 + cc4);
            CP16(st + offA1,        Ag + (size_t)rc1 * EMB + k0 + cc4);
            CP16(st + offB + offA0, Wg + (size_t)rc0 * EMB + k0 + cc4);
            CP16(st + offB + offA1, Wg + (size_t)rc1 * EMB + k0 + cc4);
        }
        CP_COMMIT();           // always one group per iteration

        const float* Ab = sm + (c & 3) * STAGE_FLOATS;
        const float* Bb = Ab + 128 * SROW;

#pragma unroll
        for (int ks = 0; ks < 2; ks++) {
            const int kk = ks * 8;
            uint32_t afr[4][4], bfr[4][2];
#pragma unroll
            for (int mf = 0; mf < 4; mf++) {
                const int m0 = wm * 64 + mf * 16 + g;
                afr[mf][0] = __float_as_uint(Ab[m0 * SROW + kk + tig]);
                afr[mf][1] = __float_as_uint(Ab[(m0 + 8) * SROW + kk + tig]);
                afr[mf][2] = __float_as_uint(Ab[m0 * SROW + kk + tig + 4]);
                afr[mf][3] = __float_as_uint(Ab[(m0 + 8) * SROW + kk + tig + 4]);
            }
#pragma unroll
            for (int nf = 0; nf < 4; nf++) {
                const int n0 = wn * 32 + nf * 8 + g;
                bfr[nf][0] = __float_as_uint(Bb[n0 * SROW + kk + tig]);
                bfr[nf][1] = __float_as_uint(Bb[n0 * SROW + kk + tig + 4]);
            }
#pragma unroll
            for (int mf = 0; mf < 4; mf++)
#pragma unroll
                for (int nf = 0; nf < 4; nf++)
                    MMA_TF32(acc[mf][nf], afr[mf], bfr[nf]);
        }
    }

    // Epilogue: bias + layout remap, float2 stores
#pragma unroll
    for (int mf = 0; mf < 4; mf++) {
#pragma unroll
        for (int nf = 0; nf < 4; nf++) {
            const int r0 = bm + wm * 64 + mf * 16 + g;
            const int r1 = r0 + 8;
            const int cc = bn + wn * 32 + nf * 8 + tig * 2;
            const float bi0 = bias[cc];
            const float bi1 = bias[cc + 1];
            float2 v0 = make_float2(acc[mf][nf][0] + bi0, acc[mf][nf][1] + bi1);
            float2 v1 = make_float2(acc[mf][nf][2] + bi0, acc[mf][nf][3] + bi1);
            if (LAYOUT == 0) {
                *reinterpret_cast<float2*>(C + (size_t)r0 * EMB + cc) = v0;
                *reinterpret_cast<float2*>(C + (size_t)r1 * EMB + cc) = v1;
            } else {
                const int hh = cc >> 6;
                const int dd = cc & 63;
                {
                    const int bb = r0 >> 11, ss = r0 & 2047;
                    *reinterpret_cast<float2*>(
                        C + (((size_t)(bb * NHEAD + hh) << 11) + ss) * HDIM + dd) = v0;
                }
                {
                    const int bb = r1 >> 11, ss = r1 & 2047;
                    *reinterpret_cast<float2*>(
                        C + (((size_t)(bb * NHEAD + hh) << 11) + ss) * HDIM + dd) = v1;
                }
            }
        }
    }
}

// ---------------------------------------------------------------------------
// tf32 mma.sync causal flash attention (R4-proven; output now pre-rounded
// to tf32 so the final GEMM needs no conversion).
// ---------------------------------------------------------------------------
#define SQ 68
#define SKS 68
#define SV 72
#define SP 68
#define ATTN_SMEM ((64*SQ + 64*SKS + 64*SV + 64*SP) * 4)   // 70656 bytes

__global__ __launch_bounds__(128, 3)
void attn_mma(const float* __restrict__ Q,
              const float* __restrict__ K,
              const float* __restrict__ V,
              float* __restrict__ O)
{
    extern __shared__ float sm[];
    float* Qs = sm;                       // [64][SQ]
    float* Ks = sm + 64 * SQ;             // [64][SKS]
    float* Vs = Ks + 64 * SKS;            // [64][SV]
    float* Ps = Vs + 64 * SV;             // [64][SP]

    const int tid  = threadIdx.x;
    const int lane = tid & 31;
    const int wid  = tid >> 5;            // 0..3
    const int g    = lane >> 2;           // 0..7
    const int tig  = lane & 3;            // 0..3
    const int m0   = wid * 16;

    const int bh = blockIdx.y;
    const int qt = (int)gridDim.x - 1 - (int)blockIdx.x;   // heavy tiles first
    const int q0 = qt << 6;

    const float* qp = Q + (size_t)bh * S_LEN * HDIM;
    const float* kp = K + (size_t)bh * S_LEN * HDIM;
    const float* vp = V + (size_t)bh * S_LEN * HDIM;

    const float QSCALE = 0.125f * 1.4426950408889634f;   // sm_scale * log2(e)

    const int row0 = tid >> 4;            // 0..7
    const int c4   = (tid & 15) << 2;     // 0..60

#pragma unroll
    for (int i = 0; i < 8; i++) {
        const int r = row0 + i * 8;
        float4 v = *reinterpret_cast<const float4*>(qp + (size_t)(q0 + r) * HDIM + c4);
        float4 o;
        o.x = tf32rf(v.x * QSCALE); o.y = tf32rf(v.y * QSCALE);
        o.z = tf32rf(v.z * QSCALE); o.w = tf32rf(v.w * QSCALE);
        *reinterpret_cast<float4*>(&Qs[r * SQ + c4]) = o;
    }

    float mr[2] = {-1e30f, -1e30f};
    float lr[2] = {0.f, 0.f};
    float oacc[8][4];
#pragma unroll
    for (int nf = 0; nf < 8; nf++)
#pragma unroll
        for (int r = 0; r < 4; r++) oacc[nf][r] = 0.f;

#pragma unroll 1
    for (int kt = 0; kt <= qt; kt++) {
        const int k0 = kt << 6;
        __syncthreads();

#pragma unroll
        for (int i = 0; i < 8; i++) {
            const int r = row0 + i * 8;
            float4 kv = *reinterpret_cast<const float4*>(kp + (size_t)(k0 + r) * HDIM + c4);
            float4 ko;
            ko.x = tf32rf(kv.x); ko.y = tf32rf(kv.y);
            ko.z = tf32rf(kv.z); ko.w = tf32rf(kv.w);
            *reinterpret_cast<float4*>(&Ks[r * SKS + c4]) = ko;
            float4 vv = *reinterpret_cast<const float4*>(vp + (size_t)(k0 + r) * HDIM + c4);
            float4 vo;
            vo.x = tf32rf(vv.x); vo.y = tf32rf(vv.y);
            vo.z = tf32rf(vv.z); vo.w = tf32rf(vv.w);
            *reinterpret_cast<float4*>(&Vs[r * SV + c4]) = vo;
        }
        __syncthreads();

        float s[8][4];
#pragma unroll
        for (int nf = 0; nf < 8; nf++)
#pragma unroll
            for (int r = 0; r < 4; r++) s[nf][r] = 0.f;

#pragma unroll
        for (int ks = 0; ks < 8; ks++) {
            const int kk = ks * 8;
            uint32_t a[4];
            a[0] = __float_as_uint(Qs[(m0 + g) * SQ + kk + tig]);
            a[1] = __float_as_uint(Qs[(m0 + g + 8) * SQ + kk + tig]);
            a[2] = __float_as_uint(Qs[(m0 + g) * SQ + kk + tig + 4]);
            a[3] = __float_as_uint(Qs[(m0 + g + 8) * SQ + kk + tig + 4]);
#pragma unroll
            for (int nf = 0; nf < 8; nf++) {
                uint32_t b[2];
                b[0] = __float_as_uint(Ks[(nf * 8 + g) * SKS + kk + tig]);
                b[1] = __float_as_uint(Ks[(nf * 8 + g) * SKS + kk + tig + 4]);
                MMA_TF32(s[nf], a, b);
            }
        }

        if (kt == qt) {
            const int r0l = m0 + g;
            const int r1l = r0l + 8;
#pragma unroll
            for (int nf = 0; nf < 8; nf++) {
                const int c0 = nf * 8 + 2 * tig;
                if (c0     > r0l) s[nf][0] = -1e30f;
                if (c0 + 1 > r0l) s[nf][1] = -1e30f;
                if (c0     > r1l) s[nf][2] = -1e30f;
                if (c0 + 1 > r1l) s[nf][3] = -1e30f;
            }
        }

#pragma unroll
        for (int r = 0; r < 2; r++) {
            float mx = -1e30f;
#pragma unroll
            for (int nf = 0; nf < 8; nf++)
                mx = fmaxf(mx, fmaxf(s[nf][2 * r], s[nf][2 * r + 1]));
            mx = fmaxf(mx, __shfl_xor_sync(0xffffffffu, mx, 1));
            mx = fmaxf(mx, __shfl_xor_sync(0xffffffffu, mx, 2));

            const float mnew = fmaxf(mr[r], mx);
            const float resc = exp2_poly(mr[r] - mnew);
            mr[r] = mnew;

            float sum = 0.f;
#pragma unroll
            for (int nf = 0; nf < 8; nf++) {
#pragma unroll
                for (int u = 0; u < 2; u++) {
                    float p = exp2_poly(s[nf][2 * r + u] - mnew);
                    p = __uint_as_float(__float_as_uint(p) & 0xFFFFE000u);  // tf32 trunc
                    s[nf][2 * r + u] = p;
                    sum += p;
                }
            }
            sum += __shfl_xor_sync(0xffffffffu, sum, 1);
            sum += __shfl_xor_sync(0xffffffffu, sum, 2);

            lr[r] = lr[r] * resc + sum;
#pragma unroll
            for (int nf = 0; nf < 8; nf++) {
                oacc[nf][2 * r]     *= resc;
                oacc[nf][2 * r + 1] *= resc;
            }
        }

#pragma unroll
        for (int nf = 0; nf < 8; nf++) {
#pragma unroll
            for (int r = 0; r < 2; r++) {
                float2 pv = make_float2(s[nf][2 * r], s[nf][2 * r + 1]);
                *reinterpret_cast<float2*>(&Ps[(m0 + g + 8 * r) * SP + nf * 8 + 2 * tig]) = pv;
            }
        }
        __syncwarp();

#pragma unroll
        for (int ks = 0; ks < 8; ks++) {
            const int kk = ks * 8;
            uint32_t a[4];
            a[0] = __float_as_uint(Ps[(m0 + g) * SP + kk + tig]);
            a[1] = __float_as_uint(Ps[(m0 + g + 8) * SP + kk + tig]);
            a[2] = __float_as_uint(Ps[(m0 + g) * SP + kk + tig + 4]);
            a[3] = __float_as_uint(Ps[(m0 + g + 8) * SP + kk + tig + 4]);
#pragma unroll
            for (int nf = 0; nf < 8; nf++) {
                uint32_t b[2];
                b[0] = __float_as_uint(Vs[(kk + tig) * SV + nf * 8 + g]);
                b[1] = __float_as_uint(Vs[(kk + tig + 4) * SV + nf * 8 + g]);
                MMA_TF32(oacc[nf], a, b);
            }
        }
    }

    const int b = bh >> 4;
    const int h = bh & 15;
    const float inv0 = 1.f / lr[0];
    const float inv1 = 1.f / lr[1];
    float* ob = O + ((size_t)(b * S_LEN + q0 + m0 + g)) * EMB + h * HDIM + 2 * tig;
#pragma unroll
    for (int nf = 0; nf < 8; nf++) {
        // write tf32-rounded so the final GEMM consumes without conversion
        float2 v0 = make_float2(tf32rf(oacc[nf][0] * inv0), tf32rf(oacc[nf][1] * inv0));
        float2 v1 = make_float2(tf32rf(oacc[nf][2] * inv1), tf32rf(oacc[nf][3] * inv1));
        *reinterpret_cast<float2*>(ob + nf * 8)                     = v0;
        *reinterpret_cast<float2*>(ob + (size_t)8 * EMB + nf * 8)   = v1;
    }
}

// ---------------------------------------------------------------------------
// Launcher
// ---------------------------------------------------------------------------
extern "C" void kernel_launch(void* const* d_in, const int* in_sizes, int n_in,
                              void* d_out, int out_size)
{
    const float* x  = (const float*)d_in[0];
    const float* Wq = (const float*)d_in[1];
    const float* bq = (const float*)d_in[2];
    const float* Wk = (const float*)d_in[3];
    const float* bk = (const float*)d_in[4];
    const float* Wv = (const float*)d_in[5];
    const float* bv = (const float*)d_in[6];
    const float* Wo = (const float*)d_in[7];
    const float* bo = (const float*)d_in[8];
    float* out = (float*)d_out;

    float *q, *k, *v, *attn, *xr, *wq, *wk, *wv, *wo;
    cudaGetSymbolAddress((void**)&q,    g_q);
    cudaGetSymbolAddress((void**)&k,    g_k);
    cudaGetSymbolAddress((void**)&v,    g_v);
    cudaGetSymbolAddress((void**)&attn, g_attn);
    cudaGetSymbolAddress((void**)&xr,   g_xr);
    cudaGetSymbolAddress((void**)&wq,   g_wq);
    cudaGetSymbolAddress((void**)&wk,   g_wk);
    cudaGetSymbolAddress((void**)&wv,   g_wv);
    cudaGetSymbolAddress((void**)&wo,   g_wo);

    cudaFuncSetAttribute(gemm_cp<0>, cudaFuncAttributeMaxDynamicSharedMemorySize, GEMM_SMEM);
    cudaFuncSetAttribute(gemm_cp<1>, cudaFuncAttributeMaxDynamicSharedMemorySize, GEMM_SMEM);
    cudaFuncSetAttribute(attn_mma, cudaFuncAttributeMaxDynamicSharedMemorySize, ATTN_SMEM);

    // Pre-round inputs to tf32 (RN) once
    const int nx4 = MROWS * EMB / 4;   // 1048576
    const int nw4 = EMB * EMB / 4;     // 262144
    round_tf32<<<nx4 / 256, 256>>>((const float4*)x,  (float4*)xr, nx4);
    round_tf32<<<nw4 / 256, 256>>>((const float4*)Wq, (float4*)wq, nw4);
    round_tf32<<<nw4 / 256, 256>>>((const float4*)Wk, (float4*)wk, nw4);
    round_tf32<<<nw4 / 256, 256>>>((const float4*)Wv, (float4*)wv, nw4);
    round_tf32<<<nw4 / 256, 256>>>((const float4*)Wo, (float4*)wo, nw4);

    dim3 gg(EMB / 128, MROWS / 128);   // (8, 32)
    gemm_cp<1><<<gg, 256, GEMM_SMEM>>>(xr, wq, bq, q);
    gemm_cp<1><<<gg, 256, GEMM_SMEM>>>(xr, wk, bk, k);
    gemm_cp<1><<<gg, 256, GEMM_SMEM>>>(xr, wv, bv, v);

    dim3 ga(S_LEN / 64, BATCH * NHEAD);   // (32, 32)
    attn_mma<<<ga, 128, ATTN_SMEM>>>(q, k, v, attn);

    gemm_cp<0><<<gg, 256, GEMM_SMEM>>>(attn, wo, bo, out);
}

// round 7
// speedup vs baseline: 3.3664x; 1.0796x over previous
#include <cuda_runtime.h>
#include <cstdint>

// ---------------------------------------------------------------------------
// Problem constants
// ---------------------------------------------------------------------------
#define S_LEN  2048
#define NHEAD  16
#define HDIM   64
#define BATCH  2
#define EMB    1024
#define MROWS  (BATCH * S_LEN)   // 4096

// ---------------------------------------------------------------------------
// Scratch (allocation-free rule: __device__ globals)
// ---------------------------------------------------------------------------
__device__ __align__(16) float g_q[(size_t)MROWS * EMB];
__device__ __align__(16) float g_k[(size_t)MROWS * EMB];
__device__ __align__(16) float g_v[(size_t)MROWS * EMB];
__device__ __align__(16) float g_attn[(size_t)MROWS * EMB];
__device__ __align__(16) float g_xr[(size_t)MROWS * EMB];     // rounded x
__device__ __align__(16) float g_wq[(size_t)EMB * EMB];       // rounded weights
__device__ __align__(16) float g_wk[(size_t)EMB * EMB];
__device__ __align__(16) float g_wv[(size_t)EMB * EMB];
__device__ __align__(16) float g_wo[(size_t)EMB * EMB];

// ---------------------------------------------------------------------------
// helpers (base ISA, sm_80+)
// ---------------------------------------------------------------------------
__device__ __forceinline__ uint32_t smem_u32(const void* p) {
    uint32_t a;
    asm("{ .reg .u64 t; cvta.to.shared.u64 t, %1; cvt.u32.u64 %0, t; }" : "=r"(a) : "l"(p));
    return a;
}
__device__ __forceinline__ uint32_t tf32r(float x) {   // round-to-nearest tf32
    uint32_t o;
    asm("cvt.rna.tf32.f32 %0, %1;" : "=r"(o) : "f"(x));
    return o;
}
__device__ __forceinline__ float tf32rf(float x) { return __uint_as_float(tf32r(x)); }

#define MMA_TF32(d, a, b)                                                   \
    asm volatile("mma.sync.aligned.m16n8k8.row.col.f32.tf32.tf32.f32 "      \
        "{%0,%1,%2,%3}, {%4,%5,%6,%7}, {%8,%9}, {%0,%1,%2,%3};"             \
        : "+f"((d)[0]), "+f"((d)[1]), "+f"((d)[2]), "+f"((d)[3])            \
        : "r"((a)[0]), "r"((a)[1]), "r"((a)[2]), "r"((a)[3]),               \
          "r"((b)[0]), "r"((b)[1]))

#define CP16(dst, src) \
    asm volatile("cp.async.cg.shared.global [%0], [%1], 16;" :: "r"(dst), "l"(src))
#define CP_COMMIT() asm volatile("cp.async.commit_group;" ::: "memory")
#define CP_WAIT1()  asm volatile("cp.async.wait_group 1;" ::: "memory")
#define CP_WAIT2()  asm volatile("cp.async.wait_group 2;" ::: "memory")

// exp2 on the FMA pipe: no MUFU, no CVT. x must be <= 0.
__device__ __forceinline__ float exp2_poly(float x) {
    x = fmaxf(x, -126.f);
    float y = x + 12582912.f;              // 1.5 * 2^23
    int   iy = __float_as_int(y);
    float n  = y - 12582912.f;
    float f  = x - n;                      // f in [-0.5, 0.5]
    float p  = 0.0013333558f;
    p = fmaf(p, f, 0.0096181291f);
    p = fmaf(p, f, 0.0555041086f);
    p = fmaf(p, f, 0.2402265069f);
    p = fmaf(p, f, 0.6931471806f);
    p = fmaf(p, f, 1.0f);
    return __int_as_float((iy + 127) << 23) * p;
}

#define QSCALE (0.125f * 1.4426950408889634f)   // sm_scale * log2(e)

// ---------------------------------------------------------------------------
// Pre-round fp32 -> tf32(RN) elementwise
// ---------------------------------------------------------------------------
__global__ __launch_bounds__(256)
void round_tf32(const float4* __restrict__ in, float4* __restrict__ out, int n4)
{
    int i = blockIdx.x * blockDim.x + threadIdx.x;
    if (i < n4) {
        float4 v = in[i];
        float4 o;
        o.x = tf32rf(v.x); o.y = tf32rf(v.y);
        o.z = tf32rf(v.z); o.w = tf32rf(v.w);
        out[i] = o;
    }
}

// ---------------------------------------------------------------------------
// GEMM core (cp.async 4-stage, tf32 mma.sync), shared by both GEMM kernels.
// CTA 128x128, 8 warps (2M x 4N), warp tile 64x32, BK=16.
// ---------------------------------------------------------------------------
#define STAGES 4
#define SROW 20
#define STAGE_FLOATS (128 * SROW * 2)
#define GEMM_SMEM (STAGES * STAGE_FLOATS * 4)   // 81920 bytes

struct GemmCore {
    float acc[4][4][4];

    __device__ __forceinline__ void run(const float* __restrict__ A,
                                        const float* __restrict__ W,
                                        float* sm, int bm, int bn)
    {
        const int tid = threadIdx.x;
#pragma unroll
        for (int mf = 0; mf < 4; mf++)
#pragma unroll
            for (int nf = 0; nf < 4; nf++)
#pragma unroll
                for (int r = 0; r < 4; r++) acc[mf][nf][r] = 0.f;

        const int lane = tid & 31;
        const int wid  = tid >> 5;
        const int g    = lane >> 2;
        const int tig  = lane & 3;
        const int wm   = wid >> 2;
        const int wn   = wid & 3;

        const int rc0 = tid >> 2;
        const int rc1 = rc0 + 64;
        const int cc4 = (tid & 3) << 2;

        const float* Ag = A + (size_t)bm * EMB;
        const float* Wg = W + (size_t)bn * EMB;

        const uint32_t sbase = smem_u32(sm);
        const uint32_t offA0 = (uint32_t)(rc0 * SROW + cc4) * 4u;
        const uint32_t offA1 = (uint32_t)(rc1 * SROW + cc4) * 4u;
        const uint32_t offB  = (uint32_t)(128 * SROW) * 4u;

        const int NCH = EMB / 16;

#pragma unroll
        for (int s = 0; s < 3; s++) {
            const int k0 = s * 16;
            const uint32_t st = sbase + (uint32_t)s * STAGE_FLOATS * 4u;
            CP16(st + offA0,        Ag + (size_t)rc0 * EMB + k0 + cc4);
            CP16(st + offA1,        Ag + (size_t)rc1 * EMB + k0 + cc4);
            CP16(st + offB + offA0, Wg + (size_t)rc0 * EMB + k0 + cc4);
            CP16(st + offB + offA1, Wg + (size_t)rc1 * EMB + k0 + cc4);
            CP_COMMIT();
        }

#pragma unroll 1
        for (int c = 0; c < NCH; c++) {
            CP_WAIT2();
            __syncthreads();

            if (c + 3 < NCH) {
                const int k0 = (c + 3) * 16;
                const uint32_t st = sbase + (uint32_t)((c + 3) & 3) * STAGE_FLOATS * 4u;
                CP16(st + offA0,        Ag + (size_t)rc0 * EMB + k0 + cc4);
                CP16(st + offA1,        Ag + (size_t)rc1 * EMB + k0 + cc4);
                CP16(st + offB + offA0, Wg + (size_t)rc0 * EMB + k0 + cc4);
                CP16(st + offB + offA1, Wg + (size_t)rc1 * EMB + k0 + cc4);
            }
            CP_COMMIT();

            const float* Ab = sm + (c & 3) * STAGE_FLOATS;
            const float* Bb = Ab + 128 * SROW;

#pragma unroll
            for (int ks = 0; ks < 2; ks++) {
                const int kk = ks * 8;
                uint32_t afr[4][4], bfr[4][2];
#pragma unroll
                for (int mf = 0; mf < 4; mf++) {
                    const int m0 = wm * 64 + mf * 16 + g;
                    afr[mf][0] = __float_as_uint(Ab[m0 * SROW + kk + tig]);
                    afr[mf][1] = __float_as_uint(Ab[(m0 + 8) * SROW + kk + tig]);
                    afr[mf][2] = __float_as_uint(Ab[m0 * SROW + kk + tig + 4]);
                    afr[mf][3] = __float_as_uint(Ab[(m0 + 8) * SROW + kk + tig + 4]);
                }
#pragma unroll
                for (int nf = 0; nf < 4; nf++) {
                    const int n0 = wn * 32 + nf * 8 + g;
                    bfr[nf][0] = __float_as_uint(Bb[n0 * SROW + kk + tig]);
                    bfr[nf][1] = __float_as_uint(Bb[n0 * SROW + kk + tig + 4]);
                }
#pragma unroll
                for (int mf = 0; mf < 4; mf++)
#pragma unroll
                    for (int nf = 0; nf < 4; nf++)
                        MMA_TF32(acc[mf][nf], afr[mf], bfr[nf]);
            }
        }
    }
};

// ---------------------------------------------------------------------------
// Fused QKV projection GEMM. Grid (24, 32): blockIdx.x>>3 selects Q/K/V.
// Epilogue: (acc + bias) * scale, rounded to tf32, head-split layout.
// Q rows are pre-scaled by QSCALE so attention consumes them directly.
// ---------------------------------------------------------------------------
__global__ __launch_bounds__(256, 2)
void gemm_qkv(const float* __restrict__ A,
              const float* __restrict__ W0, const float* __restrict__ W1,
              const float* __restrict__ W2,
              const float* __restrict__ b0, const float* __restrict__ b1,
              const float* __restrict__ b2,
              float* __restrict__ C0, float* __restrict__ C1,
              float* __restrict__ C2)
{
    extern __shared__ float sm[];
    const int sel = blockIdx.x >> 3;
    const int bn  = (blockIdx.x & 7) * 128;
    const int bm  = blockIdx.y * 128;

    const float* W    = (sel == 0) ? W0 : (sel == 1) ? W1 : W2;
    const float* bias = (sel == 0) ? b0 : (sel == 1) ? b1 : b2;
    float*       C    = (sel == 0) ? C0 : (sel == 1) ? C1 : C2;
    const float scale = (sel == 0) ? QSCALE : 1.f;

    GemmCore core;
    core.run(A, W, sm, bm, bn);

    const int lane = threadIdx.x & 31;
    const int wid  = threadIdx.x >> 5;
    const int g    = lane >> 2;
    const int tig  = lane & 3;
    const int wm   = wid >> 2;
    const int wn   = wid & 3;

#pragma unroll
    for (int mf = 0; mf < 4; mf++) {
#pragma unroll
        for (int nf = 0; nf < 4; nf++) {
            const int r0 = bm + wm * 64 + mf * 16 + g;
            const int r1 = r0 + 8;
            const int cc = bn + wn * 32 + nf * 8 + tig * 2;
            const float bi0 = bias[cc];
            const float bi1 = bias[cc + 1];
            float2 v0 = make_float2(tf32rf((core.acc[mf][nf][0] + bi0) * scale),
                                    tf32rf((core.acc[mf][nf][1] + bi1) * scale));
            float2 v1 = make_float2(tf32rf((core.acc[mf][nf][2] + bi0) * scale),
                                    tf32rf((core.acc[mf][nf][3] + bi1) * scale));
            const int hh = cc >> 6;
            const int dd = cc & 63;
            {
                const int bb = r0 >> 11, ss = r0 & 2047;
                *reinterpret_cast<float2*>(
                    C + (((size_t)(bb * NHEAD + hh) << 11) + ss) * HDIM + dd) = v0;
            }
            {
                const int bb = r1 >> 11, ss = r1 & 2047;
                *reinterpret_cast<float2*>(
                    C + (((size_t)(bb * NHEAD + hh) << 11) + ss) * HDIM + dd) = v1;
            }
        }
    }
}

// ---------------------------------------------------------------------------
// Output projection GEMM (plain layout, fp32 output, no rounding).
// ---------------------------------------------------------------------------
__global__ __launch_bounds__(256, 2)
void gemm_out(const float* __restrict__ A,
              const float* __restrict__ W,
              const float* __restrict__ bias,
              float* __restrict__ C)
{
    extern __shared__ float sm[];
    const int bn = blockIdx.x * 128;
    const int bm = blockIdx.y * 128;

    GemmCore core;
    core.run(A, W, sm, bm, bn);

    const int lane = threadIdx.x & 31;
    const int wid  = threadIdx.x >> 5;
    const int g    = lane >> 2;
    const int tig  = lane & 3;
    const int wm   = wid >> 2;
    const int wn   = wid & 3;

#pragma unroll
    for (int mf = 0; mf < 4; mf++) {
#pragma unroll
        for (int nf = 0; nf < 4; nf++) {
            const int r0 = bm + wm * 64 + mf * 16 + g;
            const int r1 = r0 + 8;
            const int cc = bn + wn * 32 + nf * 8 + tig * 2;
            const float bi0 = bias[cc];
            const float bi1 = bias[cc + 1];
            float2 v0 = make_float2(core.acc[mf][nf][0] + bi0, core.acc[mf][nf][1] + bi1);
            float2 v1 = make_float2(core.acc[mf][nf][2] + bi0, core.acc[mf][nf][3] + bi1);
            *reinterpret_cast<float2*>(C + (size_t)r0 * EMB + cc) = v0;
            *reinterpret_cast<float2*>(C + (size_t)r1 * EMB + cc) = v1;
        }
    }
}

// ---------------------------------------------------------------------------
// tf32 mma.sync causal flash attention, cp.async double-buffered K/V.
// Inputs pre-scaled (Q) and pre-rounded (Q,K,V) by gemm_qkv.
// smem: Qs[64][68], Ks[2][64][68], Vs[2][64][72], Ps[64][68] = 106496 B.
// ---------------------------------------------------------------------------
#define SQ 68
#define SK 68
#define SV 72
#define SP 68
#define ATTN_SMEM ((64*SQ + 2*64*SK + 2*64*SV + 64*SP) * 4)   // 106496

__global__ __launch_bounds__(128, 2)
void attn_mma(const float* __restrict__ Q,
              const float* __restrict__ K,
              const float* __restrict__ V,
              float* __restrict__ O)
{
    extern __shared__ float sm[];
    float* Qs  = sm;                        // [64][SQ]
    float* Ksb = sm + 64 * SQ;              // [2][64][SK]
    float* Vsb = Ksb + 2 * 64 * SK;         // [2][64][SV]
    float* Ps  = Vsb + 2 * 64 * SV;         // [64][SP]

    const int tid  = threadIdx.x;
    const int lane = tid & 31;
    const int wid  = tid >> 5;
    const int g    = lane >> 2;
    const int tig  = lane & 3;
    const int m0   = wid * 16;

    const int bh = blockIdx.y;
    const int qt = (int)gridDim.x - 1 - (int)blockIdx.x;   // heavy tiles first
    const int q0 = qt << 6;

    const float* qp = Q + (size_t)bh * S_LEN * HDIM;
    const float* kp = K + (size_t)bh * S_LEN * HDIM;
    const float* vp = V + (size_t)bh * S_LEN * HDIM;

    const int row0 = tid >> 4;            // 0..7
    const int c4   = (tid & 15) << 2;     // 0..60

    const uint32_t sQ = smem_u32(sm);
    const uint32_t sK = sQ + 64 * SQ * 4;
    const uint32_t sV = sK + 2 * 64 * SK * 4;

    // prologue: Q tile + K/V tile 0  -> group 0
#pragma unroll
    for (int i = 0; i < 8; i++) {
        const int r = row0 + i * 8;
        CP16(sQ + (uint32_t)(r * SQ + c4) * 4u, qp + (size_t)(q0 + r) * HDIM + c4);
        CP16(sK + (uint32_t)(r * SK + c4) * 4u, kp + (size_t)r * HDIM + c4);
        CP16(sV + (uint32_t)(r * SV + c4) * 4u, vp + (size_t)r * HDIM + c4);
    }
    CP_COMMIT();

    float mr[2] = {-1e30f, -1e30f};
    float lr[2] = {0.f, 0.f};
    float oacc[8][4];
#pragma unroll
    for (int nf = 0; nf < 8; nf++)
#pragma unroll
        for (int r = 0; r < 4; r++) oacc[nf][r] = 0.f;

#pragma unroll 1
    for (int kt = 0; kt <= qt; kt++) {
        const int buf = kt & 1;
        __syncthreads();   // all warps done reading buf^1 (previous iteration)

        // prefetch tile kt+1 into buf^1
        if (kt < qt) {
            const int kn = (kt + 1) << 6;
            const uint32_t dK = sK + (uint32_t)((buf ^ 1) * 64 * SK) * 4u;
            const uint32_t dV = sV + (uint32_t)((buf ^ 1) * 64 * SV) * 4u;
#pragma unroll
            for (int i = 0; i < 8; i++) {
                const int r = row0 + i * 8;
                CP16(dK + (uint32_t)(r * SK + c4) * 4u, kp + (size_t)(kn + r) * HDIM + c4);
                CP16(dV + (uint32_t)(r * SV + c4) * 4u, vp + (size_t)(kn + r) * HDIM + c4);
            }
        }
        CP_COMMIT();        // always one group/iter (possibly empty)
        CP_WAIT1();         // group for tile kt (and Q) complete
        __syncthreads();

        const float* Kb = Ksb + buf * 64 * SK;
        const float* Vb = Vsb + buf * 64 * SV;

        // ---- S = Q @ K^T : m16 x n64, 8 k-steps ----
        float s[8][4];
#pragma unroll
        for (int nf = 0; nf < 8; nf++)
#pragma unroll
            for (int r = 0; r < 4; r++) s[nf][r] = 0.f;

#pragma unroll
        for (int ks = 0; ks < 8; ks++) {
            const int kk = ks * 8;
            uint32_t a[4];
            a[0] = __float_as_uint(Qs[(m0 + g) * SQ + kk + tig]);
            a[1] = __float_as_uint(Qs[(m0 + g + 8) * SQ + kk + tig]);
            a[2] = __float_as_uint(Qs[(m0 + g) * SQ + kk + tig + 4]);
            a[3] = __float_as_uint(Qs[(m0 + g + 8) * SQ + kk + tig + 4]);
#pragma unroll
            for (int nf = 0; nf < 8; nf++) {
                uint32_t b[2];
                b[0] = __float_as_uint(Kb[(nf * 8 + g) * SK + kk + tig]);
                b[1] = __float_as_uint(Kb[(nf * 8 + g) * SK + kk + tig + 4]);
                MMA_TF32(s[nf], a, b);
            }
        }

        // ---- causal mask on the diagonal tile ----
        if (kt == qt) {
            const int r0l = m0 + g;
            const int r1l = r0l + 8;
#pragma unroll
            for (int nf = 0; nf < 8; nf++) {
                const int c0 = nf * 8 + 2 * tig;
                if (c0     > r0l) s[nf][0] = -1e30f;
                if (c0 + 1 > r0l) s[nf][1] = -1e30f;
                if (c0     > r1l) s[nf][2] = -1e30f;
                if (c0 + 1 > r1l) s[nf][3] = -1e30f;
            }
        }

        // ---- online softmax (base-2; Q pre-scaled), exp on FMA pipe ----
#pragma unroll
        for (int r = 0; r < 2; r++) {
            float mx = -1e30f;
#pragma unroll
            for (int nf = 0; nf < 8; nf++)
                mx = fmaxf(mx, fmaxf(s[nf][2 * r], s[nf][2 * r + 1]));
            mx = fmaxf(mx, __shfl_xor_sync(0xffffffffu, mx, 1));
            mx = fmaxf(mx, __shfl_xor_sync(0xffffffffu, mx, 2));

            const float mnew = fmaxf(mr[r], mx);
            const float resc = exp2_poly(mr[r] - mnew);
            mr[r] = mnew;

            float sum = 0.f;
#pragma unroll
            for (int nf = 0; nf < 8; nf++) {
#pragma unroll
                for (int u = 0; u < 2; u++) {
                    float p = exp2_poly(s[nf][2 * r + u] - mnew);
                    p = __uint_as_float(__float_as_uint(p) & 0xFFFFE000u);  // tf32 trunc
                    s[nf][2 * r + u] = p;
                    sum += p;
                }
            }
            sum += __shfl_xor_sync(0xffffffffu, sum, 1);
            sum += __shfl_xor_sync(0xffffffffu, sum, 2);

            lr[r] = lr[r] * resc + sum;
#pragma unroll
            for (int nf = 0; nf < 8; nf++) {
                oacc[nf][2 * r]     *= resc;
                oacc[nf][2 * r + 1] *= resc;
            }
        }

        // ---- write P (warp-private region) ----
#pragma unroll
        for (int nf = 0; nf < 8; nf++) {
#pragma unroll
            for (int r = 0; r < 2; r++) {
                float2 pv = make_float2(s[nf][2 * r], s[nf][2 * r + 1]);
                *reinterpret_cast<float2*>(&Ps[(m0 + g + 8 * r) * SP + nf * 8 + 2 * tig]) = pv;
            }
        }
        __syncwarp();

        // ---- O += P @ V ----
#pragma unroll
        for (int ks = 0; ks < 8; ks++) {
            const int kk = ks * 8;
            uint32_t a[4];
            a[0] = __float_as_uint(Ps[(m0 + g) * SP + kk + tig]);
            a[1] = __float_as_uint(Ps[(m0 + g + 8) * SP + kk + tig]);
            a[2] = __float_as_uint(Ps[(m0 + g) * SP + kk + tig + 4]);
            a[3] = __float_as_uint(Ps[(m0 + g + 8) * SP + kk + tig + 4]);
#pragma unroll
            for (int nf = 0; nf < 8; nf++) {
                uint32_t b[2];
                b[0] = __float_as_uint(Vb[(kk + tig) * SV + nf * 8 + g]);
                b[1] = __float_as_uint(Vb[(kk + tig + 4) * SV + nf * 8 + g]);
                MMA_TF32(oacc[nf], a, b);
            }
        }
    }

    // ---- finalize: divide by l, write (B, S, H*D), tf32-rounded ----
    const int b = bh >> 4;
    const int h = bh & 15;
    const float inv0 = 1.f / lr[0];
    const float inv1 = 1.f / lr[1];
    float* ob = O + ((size_t)(b * S_LEN + q0 + m0 + g)) * EMB + h * HDIM + 2 * tig;
#pragma unroll
    for (int nf = 0; nf < 8; nf++) {
        float2 v0 = make_float2(tf32rf(oacc[nf][0] * inv0), tf32rf(oacc[nf][1] * inv0));
        float2 v1 = make_float2(tf32rf(oacc[nf][2] * inv1), tf32rf(oacc[nf][3] * inv1));
        *reinterpret_cast<float2*>(ob + nf * 8)                   = v0;
        *reinterpret_cast<float2*>(ob + (size_t)8 * EMB + nf * 8) = v1;
    }
}

// ---------------------------------------------------------------------------
// Launcher
// ---------------------------------------------------------------------------
extern "C" void kernel_launch(void* const* d_in, const int* in_sizes, int n_in,
                              void* d_out, int out_size)
{
    const float* x  = (const float*)d_in[0];
    const float* Wq = (const float*)d_in[1];
    const float* bq = (const float*)d_in[2];
    const float* Wk = (const float*)d_in[3];
    const float* bk = (const float*)d_in[4];
    const float* Wv = (const float*)d_in[5];
    const float* bv = (const float*)d_in[6];
    const float* Wo = (const float*)d_in[7];
    const float* bo = (const float*)d_in[8];
    float* out = (float*)d_out;

    float *q, *k, *v, *attn, *xr, *wq, *wk, *wv, *wo;
    cudaGetSymbolAddress((void**)&q,    g_q);
    cudaGetSymbolAddress((void**)&k,    g_k);
    cudaGetSymbolAddress((void**)&v,    g_v);
    cudaGetSymbolAddress((void**)&attn, g_attn);
    cudaGetSymbolAddress((void**)&xr,   g_xr);
    cudaGetSymbolAddress((void**)&wq,   g_wq);
    cudaGetSymbolAddress((void**)&wk,   g_wk);
    cudaGetSymbolAddress((void**)&wv,   g_wv);
    cudaGetSymbolAddress((void**)&wo,   g_wo);

    cudaFuncSetAttribute(gemm_qkv, cudaFuncAttributeMaxDynamicSharedMemorySize, GEMM_SMEM);
    cudaFuncSetAttribute(gemm_out, cudaFuncAttributeMaxDynamicSharedMemorySize, GEMM_SMEM);
    cudaFuncSetAttribute(attn_mma, cudaFuncAttributeMaxDynamicSharedMemorySize, ATTN_SMEM);

    // Pre-round inputs to tf32 (RN)
    const int nx4 = MROWS * EMB / 4;
    const int nw4 = EMB * EMB / 4;
    round_tf32<<<nx4 / 256, 256>>>((const float4*)x,  (float4*)xr, nx4);
    round_tf32<<<nw4 / 256, 256>>>((const float4*)Wq, (float4*)wq, nw4);
    round_tf32<<<nw4 / 256, 256>>>((const float4*)Wk, (float4*)wk, nw4);
    round_tf32<<<nw4 / 256, 256>>>((const float4*)Wv, (float4*)wv, nw4);
    round_tf32<<<nw4 / 256, 256>>>((const float4*)Wo, (float4*)wo, nw4);

    dim3 gqkv(24, MROWS / 128);   // (24, 32)
    gemm_qkv<<<gqkv, 256, GEMM_SMEM>>>(xr, wq, wk, wv, bq, bk, bv, q, k, v);

    dim3 ga(S_LEN / 64, BATCH * NHEAD);   // (32, 32)
    attn_mma<<<ga, 128, ATTN_SMEM>>>(q, k, v, attn);

    dim3 go(EMB / 128, MROWS / 128);   // (8, 32)
    gemm_out<<<go, 256, GEMM_SMEM>>>(attn, wo, bo, out);
}